// round 10
// baseline (speedup 1.0000x reference)
#include <cuda_runtime.h>
#include <cuda_fp16.h>
#include <math.h>
#include <stdint.h>

// ---------------- problem constants ----------------
constexpr int Bv = 8, Tv = 8, Hv = 56, Wv = 56, Cv = 192;
constexpr int NHv = 6, Lv = Hv * Wv;                // 3136
constexpr int HIDv = 4 * Cv;                        // 768
constexpr int Mv = Bv * Tv * Lv;                    // 200704 tokens
constexpr long MCl = (long)Mv * Cv;
constexpr float QSCALE = 0.17677669529663687f;      // 32^-0.5

// ---------------- device scratch ----------------
__device__ __half g_qkv[(long)Mv * 576];
__device__ __half g_a[MCl];
__device__ __half g_osp[MCl];
__device__ __half g_ot[MCl];
__device__ __half g_h[(long)Mv * HIDv];
__device__ __half g_cat[(long)Mv * 384];
__device__ __half g_whi[847872];
__device__ float g_xt_fb[MCl];
__device__ float g_xsp_fb[MCl];

// weight offsets
constexpr int WO_QKV = 0;            // 576x192
constexpr int WO_PSP = 110592;       // 192x192
constexpr int WO_PT  = 147456;       // 192x192
constexpr int WO_TF1 = 184320;       // 768x192
constexpr int WO_TF2 = 331776;       // 192x768
constexpr int WO_SF1 = 479232;       // 768x192
constexpr int WO_SF2 = 626688;       // 192x768
constexpr int WO_FUSE = 774144;      // 192x384

// ---------------- helpers ----------------
__device__ __forceinline__ uint32_t smem_u32(const void* p) {
    uint32_t a;
    asm("{ .reg .u64 t; cvta.to.shared.u64 t, %1; cvt.u32.u64 %0, t; }" : "=r"(a) : "l"(p));
    return a;
}
__device__ __forceinline__ uint32_t pack_h2(float x, float y) {
    __half2 h = __floats2half2_rn(x, y);
    return *reinterpret_cast<uint32_t*>(&h);
}

#define LDSM4(r, addr)                                                        \
    asm volatile("ldmatrix.sync.aligned.m8n8.x4.shared.b16 {%0,%1,%2,%3}, [%4];" \
        : "=r"((r)[0]), "=r"((r)[1]), "=r"((r)[2]), "=r"((r)[3]) : "r"(addr))

#define MMA_F16(c, a, b0, b1)                                                 \
    asm volatile("mma.sync.aligned.m16n8k16.row.col.f32.f16.f16.f32 "         \
        "{%0,%1,%2,%3},{%4,%5,%6,%7},{%8,%9},{%0,%1,%2,%3};"                  \
        : "+f"((c)[0]), "+f"((c)[1]), "+f"((c)[2]), "+f"((c)[3])              \
        : "r"((a)[0]), "r"((a)[1]), "r"((a)[2]), "r"((a)[3]), "r"(b0), "r"(b1))

#define CP16(smem, gptr)                                                      \
    asm volatile("cp.async.cg.shared.global [%0], [%1], 16;"                  \
        :: "r"(smem), "l"(gptr) : "memory")
#define CP_COMMIT() asm volatile("cp.async.commit_group;" ::: "memory")
#define CP_WAIT1()  asm volatile("cp.async.wait_group 1;" ::: "memory")

// ---------------- fp16 pipelined GEMM, CTA tile 128x96, K=64/stage, 3-stage ring ----
// stage = two K=32 halves, each (80B rows): A 0 (128x64B) | W 10240 (96x64B) -> 17920;
// stage total 35840; ring 3 -> 107520 B dynamic smem (2 CTAs/SM = 215KB <= 228KB).
// EM: 0 bias->fp32; 1 +qscale(cols<192)->fp16; 2 +residual->fp32 (+opt fp16 concat);
//     4 +GELU->fp16
constexpr int HALF_ST = 17920;
constexpr int STAGE = 2 * HALF_ST;
constexpr int NSTG = 3;
constexpr int DSMEM = NSTG * STAGE;

template <int KD, int EM>
__global__ void __launch_bounds__(256, 2)
mma_gemm(const __half* __restrict__ A, const __half* __restrict__ W,
         const float* __restrict__ bias, const float* __restrict__ R,
         float* __restrict__ Y, __half* __restrict__ Yh,
         __half* __restrict__ Cat, int catoff, int N) {
    extern __shared__ char sm[];
    const int tid = threadIdx.x;
    const long m0 = (long)blockIdx.x * 128;
    const int n0 = blockIdx.y * 96;
    constexpr int NS = KD / 64;
    const uint32_t smb = smem_u32(sm);

    const int ar = tid >> 1, aoff = (tid & 1) * 32;
    const int br = tid >> 1, boff = (tid & 1) * 32;
    const bool bact = tid < 192;

    auto fill = [&](int s) {
        const uint32_t sb = smb + (s % NSTG) * STAGE;
#pragma unroll
        for (int c = 0; c < 2; c++) {
            const int kg = s * 64 + c * 32;
            {
                const char* g = reinterpret_cast<const char*>(A + (m0 + ar) * (long)KD + kg) + aoff;
                uint32_t d = sb + c * HALF_ST + ar * 80 + aoff;
                CP16(d, g); CP16(d + 16, g + 16);
            }
            if (bact) {
                const char* g = reinterpret_cast<const char*>(W + (long)(n0 + br) * KD + kg) + boff;
                uint32_t d = sb + c * HALF_ST + 10240 + br * 80 + boff;
                CP16(d, g); CP16(d + 16, g + 16);
            }
        }
    };

    // mma mapping: 8 warps = 4(M) x 2(N); warp tile 32x48
    const int l = tid & 31, wid = tid >> 5;
    const int wm = wid & 3, wn = wid >> 2;
    const int arow = wm * 32 + (l & 15);
    const int acol8 = (l >> 4) * 8;
    const int brow = wn * 48 + (l & 7) + ((l >> 4) << 3);
    const int bcol8 = ((l >> 3) & 1) * 8;

    float acc[2][6][4];
#pragma unroll
    for (int i = 0; i < 2; i++)
#pragma unroll
        for (int j = 0; j < 6; j++)
#pragma unroll
            for (int k = 0; k < 4; k++) acc[i][j][k] = 0.f;

    auto mmastage = [&](int buf) {
        const uint32_t base0 = smb + buf * STAGE;
#pragma unroll
        for (int kt = 0; kt < 4; kt++) {
            const uint32_t base = base0 + (kt >> 1) * HALF_ST;
            const int k16 = (kt & 1) * 16;
            uint32_t af[2][4];
#pragma unroll
            for (int mt = 0; mt < 2; mt++)
                LDSM4(af[mt], base + (arow + mt * 16) * 80 + (k16 + acol8) * 2);
#pragma unroll
            for (int nt = 0; nt < 3; nt++) {
                uint32_t bf[4];
                LDSM4(bf, base + 10240 + (brow + nt * 16) * 80 + (k16 + bcol8) * 2);
#pragma unroll
                for (int mt = 0; mt < 2; mt++)
#pragma unroll
                    for (int jj = 0; jj < 2; jj++)
                        MMA_F16(acc[mt][nt * 2 + jj], af[mt], bf[2 * jj], bf[2 * jj + 1]);
            }
        }
    };

    fill(0); CP_COMMIT();
    fill(1); CP_COMMIT();
    for (int s = 0; s < NS; s++) {
        CP_WAIT1();
        __syncthreads();
        mmastage(s % NSTG);
        if (s + 2 < NS) fill(s + 2);
        CP_COMMIT();
    }

    // register epilogue
    const int g = l >> 2, tg = l & 3;
#pragma unroll
    for (int mt = 0; mt < 2; mt++)
#pragma unroll
        for (int nn = 0; nn < 6; nn++) {
            const int col = n0 + wn * 48 + nn * 8 + 2 * tg;
            const float b0 = bias[col], b1 = bias[col + 1];
#pragma unroll
            for (int h = 0; h < 2; h++) {
                const long row = m0 + wm * 32 + mt * 16 + g + 8 * h;
                float vx = acc[mt][nn][2 * h] + b0;
                float vy = acc[mt][nn][2 * h + 1] + b1;
                if (EM == 1) {
                    if (col < 192) { vx *= QSCALE; vy *= QSCALE; }
                    reinterpret_cast<uint32_t*>(Yh)[(row * (long)N + col) >> 1] = pack_h2(vx, vy);
                }
                if (EM == 0) {
                    *reinterpret_cast<float2*>(Y + row * (long)N + col) = make_float2(vx, vy);
                }
                if (EM == 2) {
                    float2 rv = *reinterpret_cast<const float2*>(R + row * (long)N + col);
                    vx += rv.x; vy += rv.y;
                    *reinterpret_cast<float2*>(Y + row * (long)N + col) = make_float2(vx, vy);
                    if (Cat) {
                        reinterpret_cast<uint32_t*>(Cat)[(row * 384 + catoff + col) >> 1] =
                            pack_h2(vx, vy);
                    }
                }
                if (EM == 4) {
                    vx = 0.5f * vx * (1.0f + erff(vx * 0.70710678118654752f));
                    vy = 0.5f * vy * (1.0f + erff(vy * 0.70710678118654752f));
                    reinterpret_cast<uint32_t*>(Yh)[(row * (long)N + col) >> 1] = pack_h2(vx, vy);
                }
            }
        }
}

// ---------------- combined weight preconversion (fp16 single plane) ----------------
__global__ void w_conv_all_kernel(const float* qkv_w, const float* psp_w, const float* pt_w,
                                  const float* tf1_w, const float* tf2_w, const float* sf1_w,
                                  const float* sf2_w, const float* fuse_w,
                                  __half* __restrict__ hi) {
    int i = blockIdx.x * 256 + threadIdx.x;
    if (i >= 847872) return;
    float v;
    if (i < WO_PSP)       v = qkv_w[i - WO_QKV];
    else if (i < WO_PT)   v = psp_w[i - WO_PSP];
    else if (i < WO_TF1)  v = pt_w[i - WO_PT];
    else if (i < WO_TF2)  v = tf1_w[i - WO_TF1];
    else if (i < WO_SF1)  v = tf2_w[i - WO_TF2];
    else if (i < WO_SF2)  v = sf1_w[i - WO_SF1];
    else if (i < WO_FUSE) v = sf2_w[i - WO_SF2];
    else                  v = fuse_w[i - WO_FUSE];
    hi[i] = __float2half_rn(v);
}

// ---------------- LN fused stats+apply -> fp16 ----------------
__global__ void ln_apply_kernel(const float* __restrict__ X,
                                const float* __restrict__ gamma, const float* __restrict__ beta,
                                __half* __restrict__ O) {
    int tok = blockIdx.x * 8 + (threadIdx.x >> 5);
    int lane = threadIdx.x & 31;
    const float* p = X + (long)tok * Cv;
    float v[6];
#pragma unroll
    for (int i = 0; i < 6; i++) v[i] = p[lane + i * 32];
    float s = v[0] + v[1] + v[2] + v[3] + v[4] + v[5];
#pragma unroll
    for (int o = 16; o > 0; o >>= 1) s += __shfl_xor_sync(~0u, s, o);
    float mu = s * (1.0f / Cv);
    float qv = 0.f;
#pragma unroll
    for (int i = 0; i < 6; i++) { float d = v[i] - mu; qv += d * d; }
#pragma unroll
    for (int o = 16; o > 0; o >>= 1) qv += __shfl_xor_sync(~0u, qv, o);
    float rs = rsqrtf(qv * (1.0f / Cv) + 1e-5f);
#pragma unroll
    for (int i = 0; i < 6; i++) {
        int c = lane + i * 32;
        O[(long)tok * Cv + c] = __float2half_rn((v[i] - mu) * rs * gamma[c] + beta[c]);
    }
}

// ---------------- spatial window attention (fp16 qkv in) -> fp16 out ----------------
__global__ void __launch_bounds__(128) attn_spatial_kernel(const __half* __restrict__ qkv,
                                                           __half* __restrict__ O) {
    __shared__ float qs[49][33], ks[49][33], vs[49][33];
    __shared__ float sc[49][52];
    const int gh = blockIdx.x;
    const int g = gh / 6, h = gh % 6;
    const int b = g >> 9;
    const int rem = g & 511;
    const int win = rem >> 3, t = rem & 7;
    const int wh = win >> 3, ww = win & 7;
    const int tid = threadIdx.x;
    const long frame = (long)(b * 8 + t) * Lv;

    for (int idx = tid; idx < 49 * 32; idx += 128) {
        int i = idx >> 5, j = idx & 31;
        int l = (wh * 7 + i / 7) * 56 + ww * 7 + (i % 7);
        long base = (frame + l) * 576 + h * 32 + j;
        qs[i][j] = __half2float(qkv[base]);
        ks[i][j] = __half2float(qkv[base + 192]);
        vs[i][j] = __half2float(qkv[base + 384]);
    }
    __syncthreads();

    for (int u = tid; u < 49 * 13; u += 128) {
        int i = u / 13, jb = (u % 13) * 4;
        float a0 = 0.f, a1 = 0.f, a2 = 0.f, a3 = 0.f;
        int j1 = jb + 1 < 49 ? jb + 1 : 48;
        int j2 = jb + 2 < 49 ? jb + 2 : 48;
        int j3 = jb + 3 < 49 ? jb + 3 : 48;
#pragma unroll
        for (int kk = 0; kk < 32; kk++) {
            float qv = qs[i][kk];
            a0 += qv * ks[jb][kk];
            a1 += qv * ks[j1][kk];
            a2 += qv * ks[j2][kk];
            a3 += qv * ks[j3][kk];
        }
        sc[i][jb] = a0;
        if (jb + 1 < 49) sc[i][jb + 1] = a1;
        if (jb + 2 < 49) sc[i][jb + 2] = a2;
        if (jb + 3 < 49) sc[i][jb + 3] = a3;
    }
    __syncthreads();

    if (tid < 49) {
        float mx = -1e30f;
#pragma unroll 7
        for (int j = 0; j < 49; j++) mx = fmaxf(mx, sc[tid][j]);
        float sum = 0.f;
#pragma unroll 7
        for (int j = 0; j < 49; j++) { float e = __expf(sc[tid][j] - mx); sc[tid][j] = e; sum += e; }
        float inv = 1.0f / sum;
#pragma unroll 7
        for (int j = 0; j < 49; j++) sc[tid][j] *= inv;
    }
    __syncthreads();

    for (int u = tid; u < 49 * 8; u += 128) {
        int i = u >> 3, jb = (u & 7) * 4;
        float a0 = 0.f, a1 = 0.f, a2 = 0.f, a3 = 0.f;
#pragma unroll
        for (int n = 0; n < 49; n++) {
            float s = sc[i][n];
            a0 += s * vs[n][jb + 0];
            a1 += s * vs[n][jb + 1];
            a2 += s * vs[n][jb + 2];
            a3 += s * vs[n][jb + 3];
        }
        int l = (wh * 7 + i / 7) * 56 + ww * 7 + (i % 7);
        long idx = (frame + l) * 192 + h * 32 + jb;
        *reinterpret_cast<uint2*>(O + idx) = make_uint2(pack_h2(a0, a1), pack_h2(a2, a3));
    }
}

// ---------------- temporal attention (fp16 qkv in) -> fp16 out ----------------
__global__ void __launch_bounds__(256) attn_temporal_kernel(const __half* __restrict__ qkv,
                                                            __half* __restrict__ O) {
    const int unit = blockIdx.x * 8 + (threadIdx.x >> 5);
    const int lane = threadIdx.x & 31;
    const int g = unit / 6, h = unit % 6;
    const int b = g / Lv, l = g % Lv;
    const long base0 = ((long)(b * 8) * Lv + l) * 576 + h * 32 + lane;
    const long tstride = (long)Lv * 576;

    float q[8], k[8], v[8];
#pragma unroll
    for (int t = 0; t < 8; t++) {
        long base = base0 + (long)t * tstride;
        q[t] = __half2float(qkv[base]);
        k[t] = __half2float(qkv[base + 192]);
        v[t] = __half2float(qkv[base + 384]);
    }
#pragma unroll
    for (int t1 = 0; t1 < 8; t1++) {
        float s[8];
#pragma unroll
        for (int t2 = 0; t2 < 8; t2++) s[t2] = q[t1] * k[t2];
#pragma unroll
        for (int o = 16; o > 0; o >>= 1) {
#pragma unroll
            for (int t2 = 0; t2 < 8; t2++) s[t2] += __shfl_xor_sync(~0u, s[t2], o);
        }
        float mx = s[0];
#pragma unroll
        for (int t2 = 1; t2 < 8; t2++) mx = fmaxf(mx, s[t2]);
        float sum = 0.f;
#pragma unroll
        for (int t2 = 0; t2 < 8; t2++) { s[t2] = __expf(s[t2] - mx); sum += s[t2]; }
        float inv = 1.0f / sum;
        float o = 0.f;
#pragma unroll
        for (int t2 = 0; t2 < 8; t2++) o += s[t2] * v[t2];
        O[((long)(b * 8 + t1) * Lv + l) * 192 + h * 32 + lane] = __float2half_rn(o * inv);
    }
}

// ---------------- launcher ----------------
extern "C" void kernel_launch(void* const* d_in, const int* in_sizes, int n_in,
                              void* d_out, int out_size) {
    (void)in_sizes; (void)n_in;
    const float* x        = (const float*)d_in[0];
    const float* norm1_g  = (const float*)d_in[2];
    const float* norm1_b  = (const float*)d_in[3];
    const float* qkv_w    = (const float*)d_in[4];
    const float* qkv_b    = (const float*)d_in[5];
    const float* proj_sp_w = (const float*)d_in[6];
    const float* proj_sp_b = (const float*)d_in[7];
    const float* proj_t_w = (const float*)d_in[8];
    const float* proj_t_b = (const float*)d_in[9];
    const float* norm2_g  = (const float*)d_in[10];
    const float* norm2_b  = (const float*)d_in[11];
    const float* te_fc1_w = (const float*)d_in[12];
    const float* te_fc1_b = (const float*)d_in[13];
    const float* te_fc2_w = (const float*)d_in[14];
    const float* te_fc2_b = (const float*)d_in[15];
    const float* sp_fc1_w = (const float*)d_in[16];
    const float* sp_fc1_b = (const float*)d_in[17];
    const float* sp_fc2_w = (const float*)d_in[18];
    const float* sp_fc2_b = (const float*)d_in[19];
    const float* fuse_w   = (const float*)d_in[20];
    const float* fuse_b   = (const float*)d_in[21];

    float* out = (float*)d_out;
    float *xt, *xsp;
    if ((long)out_size >= 3 * MCl) {
        xt = out + MCl;
        xsp = out + 2 * MCl;
    } else {
        void* p;
        cudaGetSymbolAddress(&p, g_xt_fb);  xt = (float*)p;
        cudaGetSymbolAddress(&p, g_xsp_fb); xsp = (float*)p;
    }
    void* p;
    cudaGetSymbolAddress(&p, g_qkv);  __half* qkv = (__half*)p;
    cudaGetSymbolAddress(&p, g_a);    __half* a = (__half*)p;
    cudaGetSymbolAddress(&p, g_osp);  __half* osp = (__half*)p;
    cudaGetSymbolAddress(&p, g_ot);   __half* ot = (__half*)p;
    cudaGetSymbolAddress(&p, g_h);    __half* hb = (__half*)p;
    cudaGetSymbolAddress(&p, g_cat);  __half* cat = (__half*)p;
    cudaGetSymbolAddress(&p, g_whi);  __half* whi = (__half*)p;

    cudaFuncSetAttribute(mma_gemm<192, 1>, cudaFuncAttributeMaxDynamicSharedMemorySize, DSMEM);
    cudaFuncSetAttribute(mma_gemm<192, 2>, cudaFuncAttributeMaxDynamicSharedMemorySize, DSMEM);
    cudaFuncSetAttribute(mma_gemm<192, 4>, cudaFuncAttributeMaxDynamicSharedMemorySize, DSMEM);
    cudaFuncSetAttribute(mma_gemm<768, 2>, cudaFuncAttributeMaxDynamicSharedMemorySize, DSMEM);
    cudaFuncSetAttribute(mma_gemm<384, 0>, cudaFuncAttributeMaxDynamicSharedMemorySize, DSMEM);

    const int MT = Mv / 128;  // 1568

    w_conv_all_kernel<<<(847872 + 255) / 256, 256>>>(
        qkv_w, proj_sp_w, proj_t_w, te_fc1_w, te_fc2_w, sp_fc1_w, sp_fc2_w, fuse_w, whi);
    ln_apply_kernel<<<Mv / 8, 256>>>(x, norm1_g, norm1_b, a);
    // QKV (N=576) -> fp16
    mma_gemm<192, 1><<<dim3(MT, 6), 256, DSMEM>>>(
        a, whi + WO_QKV, qkv_b, nullptr, nullptr, qkv, nullptr, 0, 576);
    // attention
    attn_spatial_kernel<<<4096 * 6, 128>>>(qkv, osp);
    attn_temporal_kernel<<<(Bv * Lv * 6) / 8, 256>>>(qkv, ot);
    // proj + residual
    mma_gemm<192, 2><<<dim3(MT, 2), 256, DSMEM>>>(
        osp, whi + WO_PSP, proj_sp_b, x, xsp, nullptr, nullptr, 0, 192);
    mma_gemm<192, 2><<<dim3(MT, 2), 256, DSMEM>>>(
        ot, whi + WO_PT, proj_t_b, x, xt, nullptr, nullptr, 0, 192);
    // temporal MLP (fc2 also emits concat slot 0)
    ln_apply_kernel<<<Mv / 8, 256>>>(xt, norm2_g, norm2_b, a);
    mma_gemm<192, 4><<<dim3(MT, 8), 256, DSMEM>>>(
        a, whi + WO_TF1, te_fc1_b, nullptr, nullptr, hb, nullptr, 0, HIDv);
    mma_gemm<768, 2><<<dim3(MT, 2), 256, DSMEM>>>(
        hb, whi + WO_TF2, te_fc2_b, xt, xt, nullptr, cat, 0, 192);
    // spatial MLP (fc2 emits concat slot 192)
    ln_apply_kernel<<<Mv / 8, 256>>>(xsp, norm2_g, norm2_b, a);
    mma_gemm<192, 4><<<dim3(MT, 8), 256, DSMEM>>>(
        a, whi + WO_SF1, sp_fc1_b, nullptr, nullptr, hb, nullptr, 0, HIDv);
    mma_gemm<768, 2><<<dim3(MT, 2), 256, DSMEM>>>(
        hb, whi + WO_SF2, sp_fc2_b, xsp, xsp, nullptr, cat, 192, 192);
    // fuse
    mma_gemm<384, 0><<<dim3(MT, 2), 256, DSMEM>>>(
        cat, whi + WO_FUSE, fuse_b, nullptr, out, nullptr, nullptr, 0, 192);
}

// round 11
// speedup vs baseline: 1.0884x; 1.0884x over previous
#include <cuda_runtime.h>
#include <cuda_fp16.h>
#include <math.h>
#include <stdint.h>

// ---------------- problem constants ----------------
constexpr int Bv = 8, Tv = 8, Hv = 56, Wv = 56, Cv = 192;
constexpr int NHv = 6, Lv = Hv * Wv;                // 3136
constexpr int HIDv = 4 * Cv;                        // 768
constexpr int Mv = Bv * Tv * Lv;                    // 200704 tokens
constexpr long MCl = (long)Mv * Cv;
constexpr float QSCALE = 0.17677669529663687f;      // 32^-0.5

// ---------------- device scratch ----------------
__device__ __half g_qkv[(long)Mv * 576];
__device__ __half g_a[MCl];
__device__ __half g_osp[MCl];
__device__ __half g_ot[MCl];
__device__ __half g_h[(long)Mv * HIDv];
__device__ __half g_cat[(long)Mv * 384];
__device__ __half g_whi[847872];
__device__ float g_xt_fb[MCl];
__device__ float g_xsp_fb[MCl];

// weight offsets
constexpr int WO_QKV = 0;            // 576x192
constexpr int WO_PSP = 110592;       // 192x192
constexpr int WO_PT  = 147456;       // 192x192
constexpr int WO_TF1 = 184320;       // 768x192
constexpr int WO_TF2 = 331776;       // 192x768
constexpr int WO_SF1 = 479232;       // 768x192
constexpr int WO_SF2 = 626688;       // 192x768
constexpr int WO_FUSE = 774144;      // 192x384

// ---------------- helpers ----------------
__device__ __forceinline__ uint32_t smem_u32(const void* p) {
    uint32_t a;
    asm("{ .reg .u64 t; cvta.to.shared.u64 t, %1; cvt.u32.u64 %0, t; }" : "=r"(a) : "l"(p));
    return a;
}
__device__ __forceinline__ uint32_t pack_h2(float x, float y) {
    __half2 h = __floats2half2_rn(x, y);
    return *reinterpret_cast<uint32_t*>(&h);
}

#define LDSM4(r, addr)                                                        \
    asm volatile("ldmatrix.sync.aligned.m8n8.x4.shared.b16 {%0,%1,%2,%3}, [%4];" \
        : "=r"((r)[0]), "=r"((r)[1]), "=r"((r)[2]), "=r"((r)[3]) : "r"(addr))

#define MMA_F16(c, a, b0, b1)                                                 \
    asm volatile("mma.sync.aligned.m16n8k16.row.col.f32.f16.f16.f32 "         \
        "{%0,%1,%2,%3},{%4,%5,%6,%7},{%8,%9},{%0,%1,%2,%3};"                  \
        : "+f"((c)[0]), "+f"((c)[1]), "+f"((c)[2]), "+f"((c)[3])              \
        : "r"((a)[0]), "r"((a)[1]), "r"((a)[2]), "r"((a)[3]), "r"(b0), "r"(b1))

#define CP16(smem, gptr)                                                      \
    asm volatile("cp.async.cg.shared.global [%0], [%1], 16;"                  \
        :: "r"(smem), "l"(gptr) : "memory")
#define CP_COMMIT() asm volatile("cp.async.commit_group;" ::: "memory")
#define CP_WAIT1()  asm volatile("cp.async.wait_group 1;" ::: "memory")

// ---------------- fp16 pipelined GEMM, CTA tile 128x96, K=32/stage, 3-stage ring ----
// smem stage (80B rows): A 0 (128x64B) | W 10240 (96x64B); stage 17920
// EM: 0 bias->fp32; 1 +qscale(cols<192)->fp16; 2 +residual->fp32 (+opt fp16 concat);
//     4 +GELU->fp16
constexpr int STAGE = 17920;
constexpr int NSTG = 3;
constexpr int DSMEM = NSTG * STAGE;

template <int KD, int EM>
__global__ void __launch_bounds__(256, 2)
mma_gemm(const __half* __restrict__ A, const __half* __restrict__ W,
         const float* __restrict__ bias, const float* __restrict__ R,
         float* __restrict__ Y, __half* __restrict__ Yh,
         __half* __restrict__ Cat, int catoff, int N) {
    extern __shared__ char sm[];
    const int tid = threadIdx.x;
    const long m0 = (long)blockIdx.x * 128;
    const int n0 = blockIdx.y * 96;
    constexpr int NS = KD / 32;
    const uint32_t smb = smem_u32(sm);

    const int ar = tid >> 1, aoff = (tid & 1) * 32;
    const int br = tid >> 1, boff = (tid & 1) * 32;
    const bool bact = tid < 192;

    auto fill = [&](int s) {
        const int buf = s % NSTG;
        const uint32_t sb = smb + buf * STAGE;
        {
            const char* g = reinterpret_cast<const char*>(A + (m0 + ar) * (long)KD + s * 32) + aoff;
            uint32_t d = sb + ar * 80 + aoff;
            CP16(d, g); CP16(d + 16, g + 16);
        }
        if (bact) {
            const char* g = reinterpret_cast<const char*>(W + (long)(n0 + br) * KD + s * 32) + boff;
            uint32_t d = sb + 10240 + br * 80 + boff;
            CP16(d, g); CP16(d + 16, g + 16);
        }
    };

    // mma mapping: 8 warps = 4(M) x 2(N); warp tile 32x48
    const int l = tid & 31, wid = tid >> 5;
    const int wm = wid & 3, wn = wid >> 2;
    const int arow = wm * 32 + (l & 15);
    const int acol8 = (l >> 4) * 8;
    const int brow = wn * 48 + (l & 7) + ((l >> 4) << 3);
    const int bcol8 = ((l >> 3) & 1) * 8;

    float acc[2][6][4];
#pragma unroll
    for (int i = 0; i < 2; i++)
#pragma unroll
        for (int j = 0; j < 6; j++)
#pragma unroll
            for (int k = 0; k < 4; k++) acc[i][j][k] = 0.f;

    auto mmastage = [&](int buf) {
        const uint32_t base = smb + buf * STAGE;
#pragma unroll
        for (int kt = 0; kt < 2; kt++) {
            uint32_t af[2][4];
#pragma unroll
            for (int mt = 0; mt < 2; mt++)
                LDSM4(af[mt], base + (arow + mt * 16) * 80 + (kt * 16 + acol8) * 2);
#pragma unroll
            for (int nt = 0; nt < 3; nt++) {
                uint32_t bf[4];
                LDSM4(bf, base + 10240 + (brow + nt * 16) * 80 + (kt * 16 + bcol8) * 2);
#pragma unroll
                for (int mt = 0; mt < 2; mt++)
#pragma unroll
                    for (int jj = 0; jj < 2; jj++)
                        MMA_F16(acc[mt][nt * 2 + jj], af[mt], bf[2 * jj], bf[2 * jj + 1]);
            }
        }
    };

    fill(0); CP_COMMIT();
    fill(1); CP_COMMIT();
    for (int s = 0; s < NS; s++) {
        CP_WAIT1();
        __syncthreads();
        mmastage(s % NSTG);
        if (s + 2 < NS) fill(s + 2);
        CP_COMMIT();
    }

    // register epilogue
    const int g = l >> 2, tg = l & 3;
#pragma unroll
    for (int mt = 0; mt < 2; mt++)
#pragma unroll
        for (int nn = 0; nn < 6; nn++) {
            const int col = n0 + wn * 48 + nn * 8 + 2 * tg;
            const float b0 = bias[col], b1 = bias[col + 1];
#pragma unroll
            for (int h = 0; h < 2; h++) {
                const long row = m0 + wm * 32 + mt * 16 + g + 8 * h;
                float vx = acc[mt][nn][2 * h] + b0;
                float vy = acc[mt][nn][2 * h + 1] + b1;
                if (EM == 1) {
                    if (col < 192) { vx *= QSCALE; vy *= QSCALE; }
                    reinterpret_cast<uint32_t*>(Yh)[(row * (long)N + col) >> 1] = pack_h2(vx, vy);
                }
                if (EM == 0) {
                    *reinterpret_cast<float2*>(Y + row * (long)N + col) = make_float2(vx, vy);
                }
                if (EM == 2) {
                    float2 rv = *reinterpret_cast<const float2*>(R + row * (long)N + col);
                    vx += rv.x; vy += rv.y;
                    *reinterpret_cast<float2*>(Y + row * (long)N + col) = make_float2(vx, vy);
                    if (Cat) {
                        reinterpret_cast<uint32_t*>(Cat)[(row * 384 + catoff + col) >> 1] =
                            pack_h2(vx, vy);
                    }
                }
                if (EM == 4) {
                    vx = 0.5f * vx * (1.0f + erff(vx * 0.70710678118654752f));
                    vy = 0.5f * vy * (1.0f + erff(vy * 0.70710678118654752f));
                    reinterpret_cast<uint32_t*>(Yh)[(row * (long)N + col) >> 1] = pack_h2(vx, vy);
                }
            }
        }
}

// ---------------- combined weight preconversion (fp16 single plane) ----------------
__global__ void w_conv_all_kernel(const float* qkv_w, const float* psp_w, const float* pt_w,
                                  const float* tf1_w, const float* tf2_w, const float* sf1_w,
                                  const float* sf2_w, const float* fuse_w,
                                  __half* __restrict__ hi) {
    int i = blockIdx.x * 256 + threadIdx.x;
    if (i >= 847872) return;
    float v;
    if (i < WO_PSP)       v = qkv_w[i - WO_QKV];
    else if (i < WO_PT)   v = psp_w[i - WO_PSP];
    else if (i < WO_TF1)  v = pt_w[i - WO_PT];
    else if (i < WO_TF2)  v = tf1_w[i - WO_TF1];
    else if (i < WO_SF1)  v = tf2_w[i - WO_TF2];
    else if (i < WO_SF2)  v = sf1_w[i - WO_SF1];
    else if (i < WO_FUSE) v = sf2_w[i - WO_SF2];
    else                  v = fuse_w[i - WO_FUSE];
    hi[i] = __float2half_rn(v);
}

// ---------------- LN fused stats+apply -> fp16 ----------------
__global__ void ln_apply_kernel(const float* __restrict__ X,
                                const float* __restrict__ gamma, const float* __restrict__ beta,
                                __half* __restrict__ O) {
    int tok = blockIdx.x * 8 + (threadIdx.x >> 5);
    int lane = threadIdx.x & 31;
    const float* p = X + (long)tok * Cv;
    float v[6];
#pragma unroll
    for (int i = 0; i < 6; i++) v[i] = p[lane + i * 32];
    float s = v[0] + v[1] + v[2] + v[3] + v[4] + v[5];
#pragma unroll
    for (int o = 16; o > 0; o >>= 1) s += __shfl_xor_sync(~0u, s, o);
    float mu = s * (1.0f / Cv);
    float qv = 0.f;
#pragma unroll
    for (int i = 0; i < 6; i++) { float d = v[i] - mu; qv += d * d; }
#pragma unroll
    for (int o = 16; o > 0; o >>= 1) qv += __shfl_xor_sync(~0u, qv, o);
    float rs = rsqrtf(qv * (1.0f / Cv) + 1e-5f);
#pragma unroll
    for (int i = 0; i < 6; i++) {
        int c = lane + i * 32;
        O[(long)tok * Cv + c] = __float2half_rn((v[i] - mu) * rs * gamma[c] + beta[c]);
    }
}

// ---------------- spatial window attention (fp16 qkv in) -> fp16 out ----------------
// launch_bounds(128, 6): cap regs (~85) so occupancy isn't register-strangled.
__global__ void __launch_bounds__(128, 6) attn_spatial_kernel(const __half* __restrict__ qkv,
                                                              __half* __restrict__ O) {
    __shared__ float qs[49][33], ks[49][33], vs[49][33];
    __shared__ float sc[49][52];
    const int gh = blockIdx.x;
    const int g = gh / 6, h = gh % 6;
    const int b = g >> 9;
    const int rem = g & 511;
    const int win = rem >> 3, t = rem & 7;
    const int wh = win >> 3, ww = win & 7;
    const int tid = threadIdx.x;
    const long frame = (long)(b * 8 + t) * Lv;

    for (int idx = tid; idx < 49 * 32; idx += 128) {
        int i = idx >> 5, j = idx & 31;
        int l = (wh * 7 + i / 7) * 56 + ww * 7 + (i % 7);
        long base = (frame + l) * 576 + h * 32 + j;
        qs[i][j] = __half2float(qkv[base]);
        ks[i][j] = __half2float(qkv[base + 192]);
        vs[i][j] = __half2float(qkv[base + 384]);
    }
    __syncthreads();

    for (int u = tid; u < 49 * 13; u += 128) {
        int i = u / 13, jb = (u % 13) * 4;
        float a0 = 0.f, a1 = 0.f, a2 = 0.f, a3 = 0.f;
        int j1 = jb + 1 < 49 ? jb + 1 : 48;
        int j2 = jb + 2 < 49 ? jb + 2 : 48;
        int j3 = jb + 3 < 49 ? jb + 3 : 48;
#pragma unroll 8
        for (int kk = 0; kk < 32; kk++) {
            float qv = qs[i][kk];
            a0 += qv * ks[jb][kk];
            a1 += qv * ks[j1][kk];
            a2 += qv * ks[j2][kk];
            a3 += qv * ks[j3][kk];
        }
        sc[i][jb] = a0;
        if (jb + 1 < 49) sc[i][jb + 1] = a1;
        if (jb + 2 < 49) sc[i][jb + 2] = a2;
        if (jb + 3 < 49) sc[i][jb + 3] = a3;
    }
    __syncthreads();

    if (tid < 49) {
        float mx = -1e30f;
#pragma unroll 1
        for (int j = 0; j < 49; j++) mx = fmaxf(mx, sc[tid][j]);
        float sum = 0.f;
#pragma unroll 1
        for (int j = 0; j < 49; j++) { float e = __expf(sc[tid][j] - mx); sc[tid][j] = e; sum += e; }
        float inv = 1.0f / sum;
#pragma unroll 1
        for (int j = 0; j < 49; j++) sc[tid][j] *= inv;
    }
    __syncthreads();

    for (int u = tid; u < 49 * 8; u += 128) {
        int i = u >> 3, jb = (u & 7) * 4;
        float a0 = 0.f, a1 = 0.f, a2 = 0.f, a3 = 0.f;
#pragma unroll 7
        for (int n = 0; n < 49; n++) {
            float s = sc[i][n];
            a0 += s * vs[n][jb + 0];
            a1 += s * vs[n][jb + 1];
            a2 += s * vs[n][jb + 2];
            a3 += s * vs[n][jb + 3];
        }
        int l = (wh * 7 + i / 7) * 56 + ww * 7 + (i % 7);
        long idx = (frame + l) * 192 + h * 32 + jb;
        *reinterpret_cast<uint2*>(O + idx) = make_uint2(pack_h2(a0, a1), pack_h2(a2, a3));
    }
}

// ---------------- temporal attention (fp16 qkv in) -> fp16 out ----------------
__global__ void __launch_bounds__(256) attn_temporal_kernel(const __half* __restrict__ qkv,
                                                            __half* __restrict__ O) {
    const int unit = blockIdx.x * 8 + (threadIdx.x >> 5);
    const int lane = threadIdx.x & 31;
    const int g = unit / 6, h = unit % 6;
    const int b = g / Lv, l = g % Lv;
    const long base0 = ((long)(b * 8) * Lv + l) * 576 + h * 32 + lane;
    const long tstride = (long)Lv * 576;

    float q[8], k[8], v[8];
#pragma unroll
    for (int t = 0; t < 8; t++) {
        long base = base0 + (long)t * tstride;
        q[t] = __half2float(qkv[base]);
        k[t] = __half2float(qkv[base + 192]);
        v[t] = __half2float(qkv[base + 384]);
    }
#pragma unroll
    for (int t1 = 0; t1 < 8; t1++) {
        float s[8];
#pragma unroll
        for (int t2 = 0; t2 < 8; t2++) s[t2] = q[t1] * k[t2];
#pragma unroll
        for (int o = 16; o > 0; o >>= 1) {
#pragma unroll
            for (int t2 = 0; t2 < 8; t2++) s[t2] += __shfl_xor_sync(~0u, s[t2], o);
        }
        float mx = s[0];
#pragma unroll
        for (int t2 = 1; t2 < 8; t2++) mx = fmaxf(mx, s[t2]);
        float sum = 0.f;
#pragma unroll
        for (int t2 = 0; t2 < 8; t2++) { s[t2] = __expf(s[t2] - mx); sum += s[t2]; }
        float inv = 1.0f / sum;
        float o = 0.f;
#pragma unroll
        for (int t2 = 0; t2 < 8; t2++) o += s[t2] * v[t2];
        O[((long)(b * 8 + t1) * Lv + l) * 192 + h * 32 + lane] = __float2half_rn(o * inv);
    }
}

// ---------------- launcher ----------------
extern "C" void kernel_launch(void* const* d_in, const int* in_sizes, int n_in,
                              void* d_out, int out_size) {
    (void)in_sizes; (void)n_in;
    const float* x        = (const float*)d_in[0];
    const float* norm1_g  = (const float*)d_in[2];
    const float* norm1_b  = (const float*)d_in[3];
    const float* qkv_w    = (const float*)d_in[4];
    const float* qkv_b    = (const float*)d_in[5];
    const float* proj_sp_w = (const float*)d_in[6];
    const float* proj_sp_b = (const float*)d_in[7];
    const float* proj_t_w = (const float*)d_in[8];
    const float* proj_t_b = (const float*)d_in[9];
    const float* norm2_g  = (const float*)d_in[10];
    const float* norm2_b  = (const float*)d_in[11];
    const float* te_fc1_w = (const float*)d_in[12];
    const float* te_fc1_b = (const float*)d_in[13];
    const float* te_fc2_w = (const float*)d_in[14];
    const float* te_fc2_b = (const float*)d_in[15];
    const float* sp_fc1_w = (const float*)d_in[16];
    const float* sp_fc1_b = (const float*)d_in[17];
    const float* sp_fc2_w = (const float*)d_in[18];
    const float* sp_fc2_b = (const float*)d_in[19];
    const float* fuse_w   = (const float*)d_in[20];
    const float* fuse_b   = (const float*)d_in[21];

    float* out = (float*)d_out;
    float *xt, *xsp;
    if ((long)out_size >= 3 * MCl) {
        xt = out + MCl;
        xsp = out + 2 * MCl;
    } else {
        void* p;
        cudaGetSymbolAddress(&p, g_xt_fb);  xt = (float*)p;
        cudaGetSymbolAddress(&p, g_xsp_fb); xsp = (float*)p;
    }
    void* p;
    cudaGetSymbolAddress(&p, g_qkv);  __half* qkv = (__half*)p;
    cudaGetSymbolAddress(&p, g_a);    __half* a = (__half*)p;
    cudaGetSymbolAddress(&p, g_osp);  __half* osp = (__half*)p;
    cudaGetSymbolAddress(&p, g_ot);   __half* ot = (__half*)p;
    cudaGetSymbolAddress(&p, g_h);    __half* hb = (__half*)p;
    cudaGetSymbolAddress(&p, g_cat);  __half* cat = (__half*)p;
    cudaGetSymbolAddress(&p, g_whi);  __half* whi = (__half*)p;

    cudaFuncSetAttribute(mma_gemm<192, 1>, cudaFuncAttributeMaxDynamicSharedMemorySize, DSMEM);
    cudaFuncSetAttribute(mma_gemm<192, 2>, cudaFuncAttributeMaxDynamicSharedMemorySize, DSMEM);
    cudaFuncSetAttribute(mma_gemm<192, 4>, cudaFuncAttributeMaxDynamicSharedMemorySize, DSMEM);
    cudaFuncSetAttribute(mma_gemm<768, 2>, cudaFuncAttributeMaxDynamicSharedMemorySize, DSMEM);
    cudaFuncSetAttribute(mma_gemm<384, 0>, cudaFuncAttributeMaxDynamicSharedMemorySize, DSMEM);

    const int MT = Mv / 128;  // 1568

    w_conv_all_kernel<<<(847872 + 255) / 256, 256>>>(
        qkv_w, proj_sp_w, proj_t_w, te_fc1_w, te_fc2_w, sp_fc1_w, sp_fc2_w, fuse_w, whi);
    ln_apply_kernel<<<Mv / 8, 256>>>(x, norm1_g, norm1_b, a);
    // QKV (N=576) -> fp16
    mma_gemm<192, 1><<<dim3(MT, 6), 256, DSMEM>>>(
        a, whi + WO_QKV, qkv_b, nullptr, nullptr, qkv, nullptr, 0, 576);
    // attention
    attn_spatial_kernel<<<4096 * 6, 128>>>(qkv, osp);
    attn_temporal_kernel<<<(Bv * Lv * 6) / 8, 256>>>(qkv, ot);
    // proj + residual
    mma_gemm<192, 2><<<dim3(MT, 2), 256, DSMEM>>>(
        osp, whi + WO_PSP, proj_sp_b, x, xsp, nullptr, nullptr, 0, 192);
    mma_gemm<192, 2><<<dim3(MT, 2), 256, DSMEM>>>(
        ot, whi + WO_PT, proj_t_b, x, xt, nullptr, nullptr, 0, 192);
    // temporal MLP (fc2 also emits concat slot 0)
    ln_apply_kernel<<<Mv / 8, 256>>>(xt, norm2_g, norm2_b, a);
    mma_gemm<192, 4><<<dim3(MT, 8), 256, DSMEM>>>(
        a, whi + WO_TF1, te_fc1_b, nullptr, nullptr, hb, nullptr, 0, HIDv);
    mma_gemm<768, 2><<<dim3(MT, 2), 256, DSMEM>>>(
        hb, whi + WO_TF2, te_fc2_b, xt, xt, nullptr, cat, 0, 192);
    // spatial MLP (fc2 emits concat slot 192)
    ln_apply_kernel<<<Mv / 8, 256>>>(xsp, norm2_g, norm2_b, a);
    mma_gemm<192, 4><<<dim3(MT, 8), 256, DSMEM>>>(
        a, whi + WO_SF1, sp_fc1_b, nullptr, nullptr, hb, nullptr, 0, HIDv);
    mma_gemm<768, 2><<<dim3(MT, 2), 256, DSMEM>>>(
        hb, whi + WO_SF2, sp_fc2_b, xsp, xsp, nullptr, cat, 192, 192);
    // fuse
    mma_gemm<384, 0><<<dim3(MT, 2), 256, DSMEM>>>(
        cat, whi + WO_FUSE, fuse_b, nullptr, out, nullptr, nullptr, 0, 192);
}

// round 12
// speedup vs baseline: 1.1040x; 1.0143x over previous
#include <cuda_runtime.h>
#include <cuda_fp16.h>
#include <math.h>
#include <stdint.h>

// ---------------- problem constants ----------------
constexpr int Bv = 8, Tv = 8, Hv = 56, Wv = 56, Cv = 192;
constexpr int NHv = 6, Lv = Hv * Wv;                // 3136
constexpr int HIDv = 4 * Cv;                        // 768
constexpr int Mv = Bv * Tv * Lv;                    // 200704 tokens
constexpr long MCl = (long)Mv * Cv;
constexpr float QSCALE = 0.17677669529663687f;      // 32^-0.5

// ---------------- device scratch ----------------
__device__ __half g_qkv[(long)Mv * 576];
__device__ __half g_a[MCl];
__device__ __half g_osp[MCl];
__device__ __half g_ot[MCl];
__device__ __half g_h[(long)Mv * HIDv];
__device__ __half g_cat[(long)Mv * 384];
__device__ __half g_whi[847872];
__device__ float g_xt_fb[MCl];
__device__ float g_xsp_fb[MCl];

// weight offsets
constexpr int WO_QKV = 0;            // 576x192
constexpr int WO_PSP = 110592;       // 192x192
constexpr int WO_PT  = 147456;       // 192x192
constexpr int WO_TF1 = 184320;       // 768x192
constexpr int WO_TF2 = 331776;       // 192x768
constexpr int WO_SF1 = 479232;       // 768x192
constexpr int WO_SF2 = 626688;       // 192x768
constexpr int WO_FUSE = 774144;      // 192x384

// ---------------- helpers ----------------
__device__ __forceinline__ uint32_t smem_u32(const void* p) {
    uint32_t a;
    asm("{ .reg .u64 t; cvta.to.shared.u64 t, %1; cvt.u32.u64 %0, t; }" : "=r"(a) : "l"(p));
    return a;
}
__device__ __forceinline__ uint32_t pack_h2(float x, float y) {
    __half2 h = __floats2half2_rn(x, y);
    return *reinterpret_cast<uint32_t*>(&h);
}

#define LDSM4(r, addr)                                                        \
    asm volatile("ldmatrix.sync.aligned.m8n8.x4.shared.b16 {%0,%1,%2,%3}, [%4];" \
        : "=r"((r)[0]), "=r"((r)[1]), "=r"((r)[2]), "=r"((r)[3]) : "r"(addr))

#define MMA_F16(c, a, b0, b1)                                                 \
    asm volatile("mma.sync.aligned.m16n8k16.row.col.f32.f16.f16.f32 "         \
        "{%0,%1,%2,%3},{%4,%5,%6,%7},{%8,%9},{%0,%1,%2,%3};"                  \
        : "+f"((c)[0]), "+f"((c)[1]), "+f"((c)[2]), "+f"((c)[3])              \
        : "r"((a)[0]), "r"((a)[1]), "r"((a)[2]), "r"((a)[3]), "r"(b0), "r"(b1))

#define CP16(smem, gptr)                                                      \
    asm volatile("cp.async.cg.shared.global [%0], [%1], 16;"                  \
        :: "r"(smem), "l"(gptr) : "memory")
#define CP_COMMIT() asm volatile("cp.async.commit_group;" ::: "memory")
#define CP_WAIT1()  asm volatile("cp.async.wait_group 1;" ::: "memory")

// ---------------- fp16 pipelined GEMM, CTA tile 128x96, K=32/stage, 3-stage ring ----
// (unchanged from round 11 — known-good configuration)
constexpr int STAGE = 17920;
constexpr int NSTG = 3;
constexpr int DSMEM = NSTG * STAGE;

template <int KD, int EM>
__global__ void __launch_bounds__(256, 2)
mma_gemm(const __half* __restrict__ A, const __half* __restrict__ W,
         const float* __restrict__ bias, const float* __restrict__ R,
         float* __restrict__ Y, __half* __restrict__ Yh,
         __half* __restrict__ Cat, int catoff, int N) {
    extern __shared__ char sm[];
    const int tid = threadIdx.x;
    const long m0 = (long)blockIdx.x * 128;
    const int n0 = blockIdx.y * 96;
    constexpr int NS = KD / 32;
    const uint32_t smb = smem_u32(sm);

    const int ar = tid >> 1, aoff = (tid & 1) * 32;
    const int br = tid >> 1, boff = (tid & 1) * 32;
    const bool bact = tid < 192;

    auto fill = [&](int s) {
        const int buf = s % NSTG;
        const uint32_t sb = smb + buf * STAGE;
        {
            const char* g = reinterpret_cast<const char*>(A + (m0 + ar) * (long)KD + s * 32) + aoff;
            uint32_t d = sb + ar * 80 + aoff;
            CP16(d, g); CP16(d + 16, g + 16);
        }
        if (bact) {
            const char* g = reinterpret_cast<const char*>(W + (long)(n0 + br) * KD + s * 32) + boff;
            uint32_t d = sb + 10240 + br * 80 + boff;
            CP16(d, g); CP16(d + 16, g + 16);
        }
    };

    const int l = tid & 31, wid = tid >> 5;
    const int wm = wid & 3, wn = wid >> 2;
    const int arow = wm * 32 + (l & 15);
    const int acol8 = (l >> 4) * 8;
    const int brow = wn * 48 + (l & 7) + ((l >> 4) << 3);
    const int bcol8 = ((l >> 3) & 1) * 8;

    float acc[2][6][4];
#pragma unroll
    for (int i = 0; i < 2; i++)
#pragma unroll
        for (int j = 0; j < 6; j++)
#pragma unroll
            for (int k = 0; k < 4; k++) acc[i][j][k] = 0.f;

    auto mmastage = [&](int buf) {
        const uint32_t base = smb + buf * STAGE;
#pragma unroll
        for (int kt = 0; kt < 2; kt++) {
            uint32_t af[2][4];
#pragma unroll
            for (int mt = 0; mt < 2; mt++)
                LDSM4(af[mt], base + (arow + mt * 16) * 80 + (kt * 16 + acol8) * 2);
#pragma unroll
            for (int nt = 0; nt < 3; nt++) {
                uint32_t bf[4];
                LDSM4(bf, base + 10240 + (brow + nt * 16) * 80 + (kt * 16 + bcol8) * 2);
#pragma unroll
                for (int mt = 0; mt < 2; mt++)
#pragma unroll
                    for (int jj = 0; jj < 2; jj++)
                        MMA_F16(acc[mt][nt * 2 + jj], af[mt], bf[2 * jj], bf[2 * jj + 1]);
            }
        }
    };

    fill(0); CP_COMMIT();
    fill(1); CP_COMMIT();
    for (int s = 0; s < NS; s++) {
        CP_WAIT1();
        __syncthreads();
        mmastage(s % NSTG);
        if (s + 2 < NS) fill(s + 2);
        CP_COMMIT();
    }

    const int g = l >> 2, tg = l & 3;
#pragma unroll
    for (int mt = 0; mt < 2; mt++)
#pragma unroll
        for (int nn = 0; nn < 6; nn++) {
            const int col = n0 + wn * 48 + nn * 8 + 2 * tg;
            const float b0 = bias[col], b1 = bias[col + 1];
#pragma unroll
            for (int h = 0; h < 2; h++) {
                const long row = m0 + wm * 32 + mt * 16 + g + 8 * h;
                float vx = acc[mt][nn][2 * h] + b0;
                float vy = acc[mt][nn][2 * h + 1] + b1;
                if (EM == 1) {
                    if (col < 192) { vx *= QSCALE; vy *= QSCALE; }
                    reinterpret_cast<uint32_t*>(Yh)[(row * (long)N + col) >> 1] = pack_h2(vx, vy);
                }
                if (EM == 0) {
                    *reinterpret_cast<float2*>(Y + row * (long)N + col) = make_float2(vx, vy);
                }
                if (EM == 2) {
                    float2 rv = *reinterpret_cast<const float2*>(R + row * (long)N + col);
                    vx += rv.x; vy += rv.y;
                    *reinterpret_cast<float2*>(Y + row * (long)N + col) = make_float2(vx, vy);
                    if (Cat) {
                        reinterpret_cast<uint32_t*>(Cat)[(row * 384 + catoff + col) >> 1] =
                            pack_h2(vx, vy);
                    }
                }
                if (EM == 4) {
                    vx = 0.5f * vx * (1.0f + erff(vx * 0.70710678118654752f));
                    vy = 0.5f * vy * (1.0f + erff(vy * 0.70710678118654752f));
                    reinterpret_cast<uint32_t*>(Yh)[(row * (long)N + col) >> 1] = pack_h2(vx, vy);
                }
            }
        }
}

// ---------------- combined weight preconversion (fp16 single plane) ----------------
__global__ void w_conv_all_kernel(const float* qkv_w, const float* psp_w, const float* pt_w,
                                  const float* tf1_w, const float* tf2_w, const float* sf1_w,
                                  const float* sf2_w, const float* fuse_w,
                                  __half* __restrict__ hi) {
    int i = blockIdx.x * 256 + threadIdx.x;
    if (i >= 847872) return;
    float v;
    if (i < WO_PSP)       v = qkv_w[i - WO_QKV];
    else if (i < WO_PT)   v = psp_w[i - WO_PSP];
    else if (i < WO_TF1)  v = pt_w[i - WO_PT];
    else if (i < WO_TF2)  v = tf1_w[i - WO_TF1];
    else if (i < WO_SF1)  v = tf2_w[i - WO_TF2];
    else if (i < WO_SF2)  v = sf1_w[i - WO_SF1];
    else if (i < WO_FUSE) v = sf2_w[i - WO_SF2];
    else                  v = fuse_w[i - WO_FUSE];
    hi[i] = __float2half_rn(v);
}

// ---------------- LN fused stats+apply -> fp16 ----------------
__global__ void ln_apply_kernel(const float* __restrict__ X,
                                const float* __restrict__ gamma, const float* __restrict__ beta,
                                __half* __restrict__ O) {
    int tok = blockIdx.x * 8 + (threadIdx.x >> 5);
    int lane = threadIdx.x & 31;
    const float* p = X + (long)tok * Cv;
    float v[6];
#pragma unroll
    for (int i = 0; i < 6; i++) v[i] = p[lane + i * 32];
    float s = v[0] + v[1] + v[2] + v[3] + v[4] + v[5];
#pragma unroll
    for (int o = 16; o > 0; o >>= 1) s += __shfl_xor_sync(~0u, s, o);
    float mu = s * (1.0f / Cv);
    float qv = 0.f;
#pragma unroll
    for (int i = 0; i < 6; i++) { float d = v[i] - mu; qv += d * d; }
#pragma unroll
    for (int o = 16; o > 0; o >>= 1) qv += __shfl_xor_sync(~0u, qv, o);
    float rs = rsqrtf(qv * (1.0f / Cv) + 1e-5f);
#pragma unroll
    for (int i = 0; i < 6; i++) {
        int c = lane + i * 32;
        O[(long)tok * Cv + c] = __float2half_rn((v[i] - mu) * rs * gamma[c] + beta[c]);
    }
}

// ---------------- spatial window attention: 4x4 register tiles, float4 smem ----------
// Arrays padded to 52 rows (rows 49..51 zeroed); row stride 36 floats (16B-aligned).
__global__ void __launch_bounds__(128, 6) attn_spatial_kernel(const __half* __restrict__ qkv,
                                                              __half* __restrict__ O) {
    __shared__ float qs[52][36], ks[52][36], vs[52][36];
    __shared__ float sc[52][56];
    const int gh = blockIdx.x;
    const int g = gh / 6, h = gh % 6;
    const int b = g >> 9;
    const int rem = g & 511;
    const int win = rem >> 3, t = rem & 7;
    const int wh = win >> 3, ww = win & 7;
    const int tid = threadIdx.x;
    const long frame = (long)(b * 8 + t) * Lv;

    // zero padding rows 49..51 (3 rows x 36 cols x 3 arrays = 324)
    for (int z = tid; z < 324; z += 128) {
        int arr = z / 108, r = 49 + (z % 108) / 36, c = z % 36;
        (arr == 0 ? qs : arr == 1 ? ks : vs)[r][c] = 0.f;
    }
    // load q/k/v (49 rows x 32)
    for (int idx = tid; idx < 49 * 32; idx += 128) {
        int i = idx >> 5, j = idx & 31;
        int l = (wh * 7 + i / 7) * 56 + ww * 7 + (i % 7);
        long base = (frame + l) * 576 + h * 32 + j;
        qs[i][j] = __half2float(qkv[base]);
        ks[i][j] = __half2float(qkv[base + 192]);
        vs[i][j] = __half2float(qkv[base + 384]);
    }
    __syncthreads();

    // scores: 13x13 groups of 4x4, float4 loads
    for (int u = tid; u < 169; u += 128) {
        const int i0 = (u / 13) * 4, j0 = (u % 13) * 4;
        float acc[4][4];
#pragma unroll
        for (int r = 0; r < 4; r++)
#pragma unroll
            for (int c = 0; c < 4; c++) acc[r][c] = 0.f;
#pragma unroll
        for (int k4 = 0; k4 < 8; k4++) {
            float4 qv[4], kv[4];
#pragma unroll
            for (int r = 0; r < 4; r++)
                qv[r] = *reinterpret_cast<const float4*>(&qs[i0 + r][k4 * 4]);
#pragma unroll
            for (int c = 0; c < 4; c++)
                kv[c] = *reinterpret_cast<const float4*>(&ks[j0 + c][k4 * 4]);
#pragma unroll
            for (int r = 0; r < 4; r++)
#pragma unroll
                for (int c = 0; c < 4; c++)
                    acc[r][c] += qv[r].x * kv[c].x + qv[r].y * kv[c].y +
                                 qv[r].z * kv[c].z + qv[r].w * kv[c].w;
        }
#pragma unroll
        for (int r = 0; r < 4; r++)
#pragma unroll
            for (int c = 0; c < 4; c++) sc[i0 + r][j0 + c] = acc[r][c];
    }
    __syncthreads();

    // softmax per row
    if (tid < 49) {
        float mx = -1e30f;
#pragma unroll 1
        for (int j = 0; j < 49; j++) mx = fmaxf(mx, sc[tid][j]);
        float sum = 0.f;
#pragma unroll 1
        for (int j = 0; j < 49; j++) { float e = __expf(sc[tid][j] - mx); sc[tid][j] = e; sum += e; }
        float inv = 1.0f / sum;
#pragma unroll 1
        for (int j = 0; j < 49; j++) sc[tid][j] *= inv;
    }
    __syncthreads();

    // AV: 13 row groups x 8 channel groups of 4
    for (int u = tid; u < 104; u += 128) {
        const int i0 = (u >> 3) * 4, jb = (u & 7) * 4;
        float acc[4][4];
#pragma unroll
        for (int r = 0; r < 4; r++)
#pragma unroll
            for (int c = 0; c < 4; c++) acc[r][c] = 0.f;
#pragma unroll 7
        for (int n = 0; n < 49; n++) {
            float4 vv = *reinterpret_cast<const float4*>(&vs[n][jb]);
#pragma unroll
            for (int r = 0; r < 4; r++) {
                float s = sc[i0 + r][n];
                acc[r][0] += s * vv.x;
                acc[r][1] += s * vv.y;
                acc[r][2] += s * vv.z;
                acc[r][3] += s * vv.w;
            }
        }
#pragma unroll
        for (int r = 0; r < 4; r++) {
            int i = i0 + r;
            if (i < 49) {
                int l = (wh * 7 + i / 7) * 56 + ww * 7 + (i % 7);
                long idx = (frame + l) * 192 + h * 32 + jb;
                *reinterpret_cast<uint2*>(O + idx) =
                    make_uint2(pack_h2(acc[r][0], acc[r][1]), pack_h2(acc[r][2], acc[r][3]));
            }
        }
    }
}

// ---------------- temporal attention (fp16 qkv in) -> fp16 out ----------------
__global__ void __launch_bounds__(256) attn_temporal_kernel(const __half* __restrict__ qkv,
                                                            __half* __restrict__ O) {
    const int unit = blockIdx.x * 8 + (threadIdx.x >> 5);
    const int lane = threadIdx.x & 31;
    const int g = unit / 6, h = unit % 6;
    const int b = g / Lv, l = g % Lv;
    const long base0 = ((long)(b * 8) * Lv + l) * 576 + h * 32 + lane;
    const long tstride = (long)Lv * 576;

    float q[8], k[8], v[8];
#pragma unroll
    for (int t = 0; t < 8; t++) {
        long base = base0 + (long)t * tstride;
        q[t] = __half2float(qkv[base]);
        k[t] = __half2float(qkv[base + 192]);
        v[t] = __half2float(qkv[base + 384]);
    }
#pragma unroll
    for (int t1 = 0; t1 < 8; t1++) {
        float s[8];
#pragma unroll
        for (int t2 = 0; t2 < 8; t2++) s[t2] = q[t1] * k[t2];
#pragma unroll
        for (int o = 16; o > 0; o >>= 1) {
#pragma unroll
            for (int t2 = 0; t2 < 8; t2++) s[t2] += __shfl_xor_sync(~0u, s[t2], o);
        }
        float mx = s[0];
#pragma unroll
        for (int t2 = 1; t2 < 8; t2++) mx = fmaxf(mx, s[t2]);
        float sum = 0.f;
#pragma unroll
        for (int t2 = 0; t2 < 8; t2++) { s[t2] = __expf(s[t2] - mx); sum += s[t2]; }
        float inv = 1.0f / sum;
        float o = 0.f;
#pragma unroll
        for (int t2 = 0; t2 < 8; t2++) o += s[t2] * v[t2];
        O[((long)(b * 8 + t1) * Lv + l) * 192 + h * 32 + lane] = __float2half_rn(o * inv);
    }
}

// ---------------- launcher ----------------
extern "C" void kernel_launch(void* const* d_in, const int* in_sizes, int n_in,
                              void* d_out, int out_size) {
    (void)in_sizes; (void)n_in;
    const float* x        = (const float*)d_in[0];
    const float* norm1_g  = (const float*)d_in[2];
    const float* norm1_b  = (const float*)d_in[3];
    const float* qkv_w    = (const float*)d_in[4];
    const float* qkv_b    = (const float*)d_in[5];
    const float* proj_sp_w = (const float*)d_in[6];
    const float* proj_sp_b = (const float*)d_in[7];
    const float* proj_t_w = (const float*)d_in[8];
    const float* proj_t_b = (const float*)d_in[9];
    const float* norm2_g  = (const float*)d_in[10];
    const float* norm2_b  = (const float*)d_in[11];
    const float* te_fc1_w = (const float*)d_in[12];
    const float* te_fc1_b = (const float*)d_in[13];
    const float* te_fc2_w = (const float*)d_in[14];
    const float* te_fc2_b = (const float*)d_in[15];
    const float* sp_fc1_w = (const float*)d_in[16];
    const float* sp_fc1_b = (const float*)d_in[17];
    const float* sp_fc2_w = (const float*)d_in[18];
    const float* sp_fc2_b = (const float*)d_in[19];
    const float* fuse_w   = (const float*)d_in[20];
    const float* fuse_b   = (const float*)d_in[21];

    float* out = (float*)d_out;
    float *xt, *xsp;
    if ((long)out_size >= 3 * MCl) {
        xt = out + MCl;
        xsp = out + 2 * MCl;
    } else {
        void* p;
        cudaGetSymbolAddress(&p, g_xt_fb);  xt = (float*)p;
        cudaGetSymbolAddress(&p, g_xsp_fb); xsp = (float*)p;
    }
    void* p;
    cudaGetSymbolAddress(&p, g_qkv);  __half* qkv = (__half*)p;
    cudaGetSymbolAddress(&p, g_a);    __half* a = (__half*)p;
    cudaGetSymbolAddress(&p, g_osp);  __half* osp = (__half*)p;
    cudaGetSymbolAddress(&p, g_ot);   __half* ot = (__half*)p;
    cudaGetSymbolAddress(&p, g_h);    __half* hb = (__half*)p;
    cudaGetSymbolAddress(&p, g_cat);  __half* cat = (__half*)p;
    cudaGetSymbolAddress(&p, g_whi);  __half* whi = (__half*)p;

    cudaFuncSetAttribute(mma_gemm<192, 1>, cudaFuncAttributeMaxDynamicSharedMemorySize, DSMEM);
    cudaFuncSetAttribute(mma_gemm<192, 2>, cudaFuncAttributeMaxDynamicSharedMemorySize, DSMEM);
    cudaFuncSetAttribute(mma_gemm<192, 4>, cudaFuncAttributeMaxDynamicSharedMemorySize, DSMEM);
    cudaFuncSetAttribute(mma_gemm<768, 2>, cudaFuncAttributeMaxDynamicSharedMemorySize, DSMEM);
    cudaFuncSetAttribute(mma_gemm<384, 0>, cudaFuncAttributeMaxDynamicSharedMemorySize, DSMEM);

    const int MT = Mv / 128;  // 1568

    w_conv_all_kernel<<<(847872 + 255) / 256, 256>>>(
        qkv_w, proj_sp_w, proj_t_w, te_fc1_w, te_fc2_w, sp_fc1_w, sp_fc2_w, fuse_w, whi);
    ln_apply_kernel<<<Mv / 8, 256>>>(x, norm1_g, norm1_b, a);
    // QKV (N=576) -> fp16
    mma_gemm<192, 1><<<dim3(MT, 6), 256, DSMEM>>>(
        a, whi + WO_QKV, qkv_b, nullptr, nullptr, qkv, nullptr, 0, 576);
    // attention
    attn_spatial_kernel<<<4096 * 6, 128>>>(qkv, osp);
    attn_temporal_kernel<<<(Bv * Lv * 6) / 8, 256>>>(qkv, ot);
    // proj + residual
    mma_gemm<192, 2><<<dim3(MT, 2), 256, DSMEM>>>(
        osp, whi + WO_PSP, proj_sp_b, x, xsp, nullptr, nullptr, 0, 192);
    mma_gemm<192, 2><<<dim3(MT, 2), 256, DSMEM>>>(
        ot, whi + WO_PT, proj_t_b, x, xt, nullptr, nullptr, 0, 192);
    // temporal MLP (fc2 also emits concat slot 0)
    ln_apply_kernel<<<Mv / 8, 256>>>(xt, norm2_g, norm2_b, a);
    mma_gemm<192, 4><<<dim3(MT, 8), 256, DSMEM>>>(
        a, whi + WO_TF1, te_fc1_b, nullptr, nullptr, hb, nullptr, 0, HIDv);
    mma_gemm<768, 2><<<dim3(MT, 2), 256, DSMEM>>>(
        hb, whi + WO_TF2, te_fc2_b, xt, xt, nullptr, cat, 0, 192);
    // spatial MLP (fc2 emits concat slot 192)
    ln_apply_kernel<<<Mv / 8, 256>>>(xsp, norm2_g, norm2_b, a);
    mma_gemm<192, 4><<<dim3(MT, 8), 256, DSMEM>>>(
        a, whi + WO_SF1, sp_fc1_b, nullptr, nullptr, hb, nullptr, 0, HIDv);
    mma_gemm<768, 2><<<dim3(MT, 2), 256, DSMEM>>>(
        hb, whi + WO_SF2, sp_fc2_b, xsp, xsp, nullptr, cat, 192, 192);
    // fuse
    mma_gemm<384, 0><<<dim3(MT, 2), 256, DSMEM>>>(
        cat, whi + WO_FUSE, fuse_b, nullptr, out, nullptr, nullptr, 0, 192);
}

// round 13
// speedup vs baseline: 1.3423x; 1.2159x over previous
#include <cuda_runtime.h>
#include <cuda_fp16.h>
#include <math.h>
#include <stdint.h>

// ---------------- problem constants ----------------
constexpr int Bv = 8, Tv = 8, Hv = 56, Wv = 56, Cv = 192;
constexpr int NHv = 6, Lv = Hv * Wv;                // 3136
constexpr int HIDv = 4 * Cv;                        // 768
constexpr int Mv = Bv * Tv * Lv;                    // 200704 tokens
constexpr long MCl = (long)Mv * Cv;
constexpr float QSCALE = 0.17677669529663687f;      // 32^-0.5

// ---------------- device scratch ----------------
__device__ __half g_qkv[(long)Mv * 576];
__device__ __half g_a[MCl];
__device__ __half g_osp[MCl];
__device__ __half g_ot[MCl];
__device__ __half g_h[(long)Mv * HIDv];
__device__ __half g_cat[(long)Mv * 384];
__device__ __half g_whi[847872];
__device__ float g_xt_fb[MCl];
__device__ float g_xsp_fb[MCl];

// weight offsets
constexpr int WO_QKV = 0;            // 576x192
constexpr int WO_PSP = 110592;       // 192x192
constexpr int WO_PT  = 147456;       // 192x192
constexpr int WO_TF1 = 184320;       // 768x192
constexpr int WO_TF2 = 331776;       // 192x768
constexpr int WO_SF1 = 479232;       // 768x192
constexpr int WO_SF2 = 626688;       // 192x768
constexpr int WO_FUSE = 774144;      // 192x384

// ---------------- helpers ----------------
__device__ __forceinline__ uint32_t smem_u32(const void* p) {
    uint32_t a;
    asm("{ .reg .u64 t; cvta.to.shared.u64 t, %1; cvt.u32.u64 %0, t; }" : "=r"(a) : "l"(p));
    return a;
}
__device__ __forceinline__ uint32_t pack_h2(float x, float y) {
    __half2 h = __floats2half2_rn(x, y);
    return *reinterpret_cast<uint32_t*>(&h);
}

#define LDSM4(r, addr)                                                        \
    asm volatile("ldmatrix.sync.aligned.m8n8.x4.shared.b16 {%0,%1,%2,%3}, [%4];" \
        : "=r"((r)[0]), "=r"((r)[1]), "=r"((r)[2]), "=r"((r)[3]) : "r"(addr))

#define LDSM4T(r, addr)                                                       \
    asm volatile("ldmatrix.sync.aligned.m8n8.x4.trans.shared.b16 {%0,%1,%2,%3}, [%4];" \
        : "=r"((r)[0]), "=r"((r)[1]), "=r"((r)[2]), "=r"((r)[3]) : "r"(addr))

#define MMA_F16(c, a, b0, b1)                                                 \
    asm volatile("mma.sync.aligned.m16n8k16.row.col.f32.f16.f16.f32 "         \
        "{%0,%1,%2,%3},{%4,%5,%6,%7},{%8,%9},{%0,%1,%2,%3};"                  \
        : "+f"((c)[0]), "+f"((c)[1]), "+f"((c)[2]), "+f"((c)[3])              \
        : "r"((a)[0]), "r"((a)[1]), "r"((a)[2]), "r"((a)[3]), "r"(b0), "r"(b1))

#define CP16(smem, gptr)                                                      \
    asm volatile("cp.async.cg.shared.global [%0], [%1], 16;"                  \
        :: "r"(smem), "l"(gptr) : "memory")
#define CP_COMMIT() asm volatile("cp.async.commit_group;" ::: "memory")
#define CP_WAIT1()  asm volatile("cp.async.wait_group 1;" ::: "memory")

// ---------------- fp16 pipelined GEMM, CTA tile 128x96, K=32/stage, 3-stage ring ----
// (frozen round-9/11 configuration — known best)
constexpr int STAGE = 17920;
constexpr int NSTG = 3;
constexpr int DSMEM = NSTG * STAGE;

template <int KD, int EM>
__global__ void __launch_bounds__(256, 2)
mma_gemm(const __half* __restrict__ A, const __half* __restrict__ W,
         const float* __restrict__ bias, const float* __restrict__ R,
         float* __restrict__ Y, __half* __restrict__ Yh,
         __half* __restrict__ Cat, int catoff, int N) {
    extern __shared__ char sm[];
    const int tid = threadIdx.x;
    const long m0 = (long)blockIdx.x * 128;
    const int n0 = blockIdx.y * 96;
    constexpr int NS = KD / 32;
    const uint32_t smb = smem_u32(sm);

    const int ar = tid >> 1, aoff = (tid & 1) * 32;
    const int br = tid >> 1, boff = (tid & 1) * 32;
    const bool bact = tid < 192;

    auto fill = [&](int s) {
        const int buf = s % NSTG;
        const uint32_t sb = smb + buf * STAGE;
        {
            const char* g = reinterpret_cast<const char*>(A + (m0 + ar) * (long)KD + s * 32) + aoff;
            uint32_t d = sb + ar * 80 + aoff;
            CP16(d, g); CP16(d + 16, g + 16);
        }
        if (bact) {
            const char* g = reinterpret_cast<const char*>(W + (long)(n0 + br) * KD + s * 32) + boff;
            uint32_t d = sb + 10240 + br * 80 + boff;
            CP16(d, g); CP16(d + 16, g + 16);
        }
    };

    const int l = tid & 31, wid = tid >> 5;
    const int wm = wid & 3, wn = wid >> 2;
    const int arow = wm * 32 + (l & 15);
    const int acol8 = (l >> 4) * 8;
    const int brow = wn * 48 + (l & 7) + ((l >> 4) << 3);
    const int bcol8 = ((l >> 3) & 1) * 8;

    float acc[2][6][4];
#pragma unroll
    for (int i = 0; i < 2; i++)
#pragma unroll
        for (int j = 0; j < 6; j++)
#pragma unroll
            for (int k = 0; k < 4; k++) acc[i][j][k] = 0.f;

    auto mmastage = [&](int buf) {
        const uint32_t base = smb + buf * STAGE;
#pragma unroll
        for (int kt = 0; kt < 2; kt++) {
            uint32_t af[2][4];
#pragma unroll
            for (int mt = 0; mt < 2; mt++)
                LDSM4(af[mt], base + (arow + mt * 16) * 80 + (kt * 16 + acol8) * 2);
#pragma unroll
            for (int nt = 0; nt < 3; nt++) {
                uint32_t bf[4];
                LDSM4(bf, base + 10240 + (brow + nt * 16) * 80 + (kt * 16 + bcol8) * 2);
#pragma unroll
                for (int mt = 0; mt < 2; mt++)
#pragma unroll
                    for (int jj = 0; jj < 2; jj++)
                        MMA_F16(acc[mt][nt * 2 + jj], af[mt], bf[2 * jj], bf[2 * jj + 1]);
            }
        }
    };

    fill(0); CP_COMMIT();
    fill(1); CP_COMMIT();
    for (int s = 0; s < NS; s++) {
        CP_WAIT1();
        __syncthreads();
        mmastage(s % NSTG);
        if (s + 2 < NS) fill(s + 2);
        CP_COMMIT();
    }

    const int g = l >> 2, tg = l & 3;
#pragma unroll
    for (int mt = 0; mt < 2; mt++)
#pragma unroll
        for (int nn = 0; nn < 6; nn++) {
            const int col = n0 + wn * 48 + nn * 8 + 2 * tg;
            const float b0 = bias[col], b1 = bias[col + 1];
#pragma unroll
            for (int h = 0; h < 2; h++) {
                const long row = m0 + wm * 32 + mt * 16 + g + 8 * h;
                float vx = acc[mt][nn][2 * h] + b0;
                float vy = acc[mt][nn][2 * h + 1] + b1;
                if (EM == 1) {
                    if (col < 192) { vx *= QSCALE; vy *= QSCALE; }
                    reinterpret_cast<uint32_t*>(Yh)[(row * (long)N + col) >> 1] = pack_h2(vx, vy);
                }
                if (EM == 0) {
                    *reinterpret_cast<float2*>(Y + row * (long)N + col) = make_float2(vx, vy);
                }
                if (EM == 2) {
                    float2 rv = *reinterpret_cast<const float2*>(R + row * (long)N + col);
                    vx += rv.x; vy += rv.y;
                    *reinterpret_cast<float2*>(Y + row * (long)N + col) = make_float2(vx, vy);
                    if (Cat) {
                        reinterpret_cast<uint32_t*>(Cat)[(row * 384 + catoff + col) >> 1] =
                            pack_h2(vx, vy);
                    }
                }
                if (EM == 4) {
                    vx = 0.5f * vx * (1.0f + erff(vx * 0.70710678118654752f));
                    vy = 0.5f * vy * (1.0f + erff(vy * 0.70710678118654752f));
                    reinterpret_cast<uint32_t*>(Yh)[(row * (long)N + col) >> 1] = pack_h2(vx, vy);
                }
            }
        }
}

// ---------------- combined weight preconversion (fp16 single plane) ----------------
__global__ void w_conv_all_kernel(const float* qkv_w, const float* psp_w, const float* pt_w,
                                  const float* tf1_w, const float* tf2_w, const float* sf1_w,
                                  const float* sf2_w, const float* fuse_w,
                                  __half* __restrict__ hi) {
    int i = blockIdx.x * 256 + threadIdx.x;
    if (i >= 847872) return;
    float v;
    if (i < WO_PSP)       v = qkv_w[i - WO_QKV];
    else if (i < WO_PT)   v = psp_w[i - WO_PSP];
    else if (i < WO_TF1)  v = pt_w[i - WO_PT];
    else if (i < WO_TF2)  v = tf1_w[i - WO_TF1];
    else if (i < WO_SF1)  v = tf2_w[i - WO_TF2];
    else if (i < WO_SF2)  v = sf1_w[i - WO_SF1];
    else if (i < WO_FUSE) v = sf2_w[i - WO_SF2];
    else                  v = fuse_w[i - WO_FUSE];
    hi[i] = __float2half_rn(v);
}

// ---------------- LN fused stats+apply -> fp16 ----------------
__global__ void ln_apply_kernel(const float* __restrict__ X,
                                const float* __restrict__ gamma, const float* __restrict__ beta,
                                __half* __restrict__ O) {
    int tok = blockIdx.x * 8 + (threadIdx.x >> 5);
    int lane = threadIdx.x & 31;
    const float* p = X + (long)tok * Cv;
    float v[6];
#pragma unroll
    for (int i = 0; i < 6; i++) v[i] = p[lane + i * 32];
    float s = v[0] + v[1] + v[2] + v[3] + v[4] + v[5];
#pragma unroll
    for (int o = 16; o > 0; o >>= 1) s += __shfl_xor_sync(~0u, s, o);
    float mu = s * (1.0f / Cv);
    float qv = 0.f;
#pragma unroll
    for (int i = 0; i < 6; i++) { float d = v[i] - mu; qv += d * d; }
#pragma unroll
    for (int o = 16; o > 0; o >>= 1) qv += __shfl_xor_sync(~0u, qv, o);
    float rs = rsqrtf(qv * (1.0f / Cv) + 1e-5f);
#pragma unroll
    for (int i = 0; i < 6; i++) {
        int c = lane + i * 32;
        O[(long)tok * Cv + c] = __float2half_rn((v[i] - mu) * rs * gamma[c] + beta[c]);
    }
}

// ---------------- spatial window attention on tensor cores ----------------
// One CTA per (window-frame, head). 128 threads = 4 warps; rows padded 49->64.
// Qs/Ks/Vs fp16 [64][40] (80B rows); sc fp32 [64][57]; Ps fp16 [64][72] (144B rows).
__global__ void __launch_bounds__(128, 4) attn_spatial_kernel(const __half* __restrict__ qkv,
                                                              __half* __restrict__ O) {
    __shared__ __half Qs[64][40], Ks[64][40], Vs[64][40];
    __shared__ float sc[64][57];
    __shared__ __half Ps[64][72];

    const int gh = blockIdx.x;
    const int g = gh / 6, h = gh % 6;
    const int b = g >> 9;
    const int rem = g & 511;
    const int win = rem >> 3, t = rem & 7;
    const int wh = win >> 3, ww = win & 7;
    const int tid = threadIdx.x;
    const int l = tid & 31, w = tid >> 5;
    const long frame = (long)(b * 8 + t) * Lv;

    // zero pads: Vs rows 49..63 (40 halfs) + Ps rows 49..63 (72 halfs)
    for (int z = tid; z < 15 * 20; z += 128)   // Vs pad as uint32: 15 rows x 20
        reinterpret_cast<uint32_t*>(&Vs[49 + z / 20][0])[z % 20] = 0;
    for (int z = tid; z < 15 * 36; z += 128)   // Ps pad as uint32: 15 rows x 36
        reinterpret_cast<uint32_t*>(&Ps[49 + z / 36][0])[z % 36] = 0;

    // load q/k/v: 49 tokens x 3 x 4 chunks of 8 halfs (16B)
    for (int u = tid; u < 49 * 12; u += 128) {
        const int i = u / 12, c = u % 12;
        const int seg = c >> 2, cc = c & 3;            // seg: 0=q,1=k,2=v
        const int ltok = (wh * 7 + i / 7) * 56 + ww * 7 + (i % 7);
        const long base = (frame + ltok) * 576 + seg * 192 + h * 32 + cc * 8;
        uint4 v = *reinterpret_cast<const uint4*>(qkv + base);
        __half* dst = (seg == 0 ? &Qs[i][0] : seg == 1 ? &Ks[i][0] : &Vs[i][0]) + cc * 8;
        *reinterpret_cast<uint4*>(dst) = v;
    }
    __syncthreads();

    const uint32_t q_b = smem_u32(Qs), k_b = smem_u32(Ks), v_b = smem_u32(Vs);
    const uint32_t p_b = smem_u32(Ps);

    // ---- scores: S[64x56] = Q @ K^T (per warp: 16 rows x 7 n-tiles) ----
    {
        float acc[7][4];
#pragma unroll
        for (int nt = 0; nt < 7; nt++)
#pragma unroll
            for (int k = 0; k < 4; k++) acc[nt][k] = 0.f;

        const int abrow = w * 16 + (l & 15);
        const int bq = (l & 7) + ((l >> 4) << 3);      // B row within n-pair
        const int bk8 = ((l >> 3) & 1) * 8;
#pragma unroll
        for (int kt = 0; kt < 2; kt++) {
            uint32_t af[4];
            LDSM4(af, q_b + abrow * 80 + (kt * 16 + (l >> 4) * 8) * 2);
#pragma unroll
            for (int np = 0; np < 4; np++) {
                uint32_t bf[4];
                LDSM4(bf, k_b + (np * 16 + bq) * 80 + (kt * 16 + bk8) * 2);
                MMA_F16(acc[np * 2], af, bf[0], bf[1]);
                if (np < 3) MMA_F16(acc[np * 2 + 1], af, bf[2], bf[3]);
            }
        }
        const int r0 = w * 16 + (l >> 2), c0 = 2 * (l & 3);
#pragma unroll
        for (int nt = 0; nt < 7; nt++) {
            sc[r0][nt * 8 + c0] = acc[nt][0];
            sc[r0][nt * 8 + c0 + 1] = acc[nt][1];
            sc[r0 + 8][nt * 8 + c0] = acc[nt][2];
            sc[r0 + 8][nt * 8 + c0 + 1] = acc[nt][3];
        }
    }
    __syncthreads();

    // ---- softmax rows 0..48 -> Ps fp16 (cols >=49 zero) ----
    if (tid < 49) {
        float mx = -1e30f;
#pragma unroll 1
        for (int j = 0; j < 49; j++) mx = fmaxf(mx, sc[tid][j]);
        float sum = 0.f;
#pragma unroll 1
        for (int j = 0; j < 49; j++) { float e = __expf(sc[tid][j] - mx); sc[tid][j] = e; sum += e; }
        float inv = 1.0f / sum;
        uint32_t* prow = reinterpret_cast<uint32_t*>(&Ps[tid][0]);
#pragma unroll 1
        for (int jj = 0; jj < 24; jj++)
            prow[jj] = pack_h2(sc[tid][2 * jj] * inv, sc[tid][2 * jj + 1] * inv);
        prow[24] = pack_h2(sc[tid][48] * inv, 0.f);
#pragma unroll
        for (int jj = 25; jj < 32; jj++) prow[jj] = 0u;
    }
    __syncthreads();

    // ---- AV: O[64x32] = P @ V (per warp: 16 rows x 4 n-tiles, K=64) ----
    {
        float acc2[4][4];
#pragma unroll
        for (int nt = 0; nt < 4; nt++)
#pragma unroll
            for (int k = 0; k < 4; k++) acc2[nt][k] = 0.f;

        const int arow = w * 16 + (l & 15);
#pragma unroll
        for (int kt = 0; kt < 4; kt++) {
            uint32_t af[4];
            LDSM4(af, p_b + arow * 144 + (kt * 16 + (l >> 4) * 8) * 2);
#pragma unroll
            for (int np = 0; np < 2; np++) {
                uint32_t bt[4];
                LDSM4T(bt, v_b + (kt * 16 + (l & 15)) * 80 + (np * 16 + ((l >> 4) & 1) * 8) * 2);
                MMA_F16(acc2[np * 2], af, bt[0], bt[1]);
                MMA_F16(acc2[np * 2 + 1], af, bt[2], bt[3]);
            }
        }
        // store: rows r0, r0+8 (token-mapped), cols h*32 + nt*8 + 2*(l&3)
        const int r0 = w * 16 + (l >> 2), c0 = 2 * (l & 3);
#pragma unroll
        for (int half = 0; half < 2; half++) {
            const int i = r0 + half * 8;
            if (i < 49) {
                const int ltok = (wh * 7 + i / 7) * 56 + ww * 7 + (i % 7);
                const long base = (frame + ltok) * 192 + h * 32;
#pragma unroll
                for (int nt = 0; nt < 4; nt++)
                    reinterpret_cast<uint32_t*>(O + base + nt * 8 + c0)[0] =
                        pack_h2(acc2[nt][2 * half], acc2[nt][2 * half + 1]);
            }
        }
    }
}

// ---------------- temporal attention (fp16 qkv in) -> fp16 out ----------------
__global__ void __launch_bounds__(256) attn_temporal_kernel(const __half* __restrict__ qkv,
                                                            __half* __restrict__ O) {
    const int unit = blockIdx.x * 8 + (threadIdx.x >> 5);
    const int lane = threadIdx.x & 31;
    const int g = unit / 6, h = unit % 6;
    const int b = g / Lv, l = g % Lv;
    const long base0 = ((long)(b * 8) * Lv + l) * 576 + h * 32 + lane;
    const long tstride = (long)Lv * 576;

    float q[8], k[8], v[8];
#pragma unroll
    for (int t = 0; t < 8; t++) {
        long base = base0 + (long)t * tstride;
        q[t] = __half2float(qkv[base]);
        k[t] = __half2float(qkv[base + 192]);
        v[t] = __half2float(qkv[base + 384]);
    }
#pragma unroll
    for (int t1 = 0; t1 < 8; t1++) {
        float s[8];
#pragma unroll
        for (int t2 = 0; t2 < 8; t2++) s[t2] = q[t1] * k[t2];
#pragma unroll
        for (int o = 16; o > 0; o >>= 1) {
#pragma unroll
            for (int t2 = 0; t2 < 8; t2++) s[t2] += __shfl_xor_sync(~0u, s[t2], o);
        }
        float mx = s[0];
#pragma unroll
        for (int t2 = 1; t2 < 8; t2++) mx = fmaxf(mx, s[t2]);
        float sum = 0.f;
#pragma unroll
        for (int t2 = 0; t2 < 8; t2++) { s[t2] = __expf(s[t2] - mx); sum += s[t2]; }
        float inv = 1.0f / sum;
        float o = 0.f;
#pragma unroll
        for (int t2 = 0; t2 < 8; t2++) o += s[t2] * v[t2];
        O[((long)(b * 8 + t1) * Lv + l) * 192 + h * 32 + lane] = __float2half_rn(o * inv);
    }
}

// ---------------- launcher ----------------
extern "C" void kernel_launch(void* const* d_in, const int* in_sizes, int n_in,
                              void* d_out, int out_size) {
    (void)in_sizes; (void)n_in;
    const float* x        = (const float*)d_in[0];
    const float* norm1_g  = (const float*)d_in[2];
    const float* norm1_b  = (const float*)d_in[3];
    const float* qkv_w    = (const float*)d_in[4];
    const float* qkv_b    = (const float*)d_in[5];
    const float* proj_sp_w = (const float*)d_in[6];
    const float* proj_sp_b = (const float*)d_in[7];
    const float* proj_t_w = (const float*)d_in[8];
    const float* proj_t_b = (const float*)d_in[9];
    const float* norm2_g  = (const float*)d_in[10];
    const float* norm2_b  = (const float*)d_in[11];
    const float* te_fc1_w = (const float*)d_in[12];
    const float* te_fc1_b = (const float*)d_in[13];
    const float* te_fc2_w = (const float*)d_in[14];
    const float* te_fc2_b = (const float*)d_in[15];
    const float* sp_fc1_w = (const float*)d_in[16];
    const float* sp_fc1_b = (const float*)d_in[17];
    const float* sp_fc2_w = (const float*)d_in[18];
    const float* sp_fc2_b = (const float*)d_in[19];
    const float* fuse_w   = (const float*)d_in[20];
    const float* fuse_b   = (const float*)d_in[21];

    float* out = (float*)d_out;
    float *xt, *xsp;
    if ((long)out_size >= 3 * MCl) {
        xt = out + MCl;
        xsp = out + 2 * MCl;
    } else {
        void* p;
        cudaGetSymbolAddress(&p, g_xt_fb);  xt = (float*)p;
        cudaGetSymbolAddress(&p, g_xsp_fb); xsp = (float*)p;
    }
    void* p;
    cudaGetSymbolAddress(&p, g_qkv);  __half* qkv = (__half*)p;
    cudaGetSymbolAddress(&p, g_a);    __half* a = (__half*)p;
    cudaGetSymbolAddress(&p, g_osp);  __half* osp = (__half*)p;
    cudaGetSymbolAddress(&p, g_ot);   __half* ot = (__half*)p;
    cudaGetSymbolAddress(&p, g_h);    __half* hb = (__half*)p;
    cudaGetSymbolAddress(&p, g_cat);  __half* cat = (__half*)p;
    cudaGetSymbolAddress(&p, g_whi);  __half* whi = (__half*)p;

    cudaFuncSetAttribute(mma_gemm<192, 1>, cudaFuncAttributeMaxDynamicSharedMemorySize, DSMEM);
    cudaFuncSetAttribute(mma_gemm<192, 2>, cudaFuncAttributeMaxDynamicSharedMemorySize, DSMEM);
    cudaFuncSetAttribute(mma_gemm<192, 4>, cudaFuncAttributeMaxDynamicSharedMemorySize, DSMEM);
    cudaFuncSetAttribute(mma_gemm<768, 2>, cudaFuncAttributeMaxDynamicSharedMemorySize, DSMEM);
    cudaFuncSetAttribute(mma_gemm<384, 0>, cudaFuncAttributeMaxDynamicSharedMemorySize, DSMEM);

    const int MT = Mv / 128;  // 1568

    w_conv_all_kernel<<<(847872 + 255) / 256, 256>>>(
        qkv_w, proj_sp_w, proj_t_w, te_fc1_w, te_fc2_w, sp_fc1_w, sp_fc2_w, fuse_w, whi);
    ln_apply_kernel<<<Mv / 8, 256>>>(x, norm1_g, norm1_b, a);
    // QKV (N=576) -> fp16
    mma_gemm<192, 1><<<dim3(MT, 6), 256, DSMEM>>>(
        a, whi + WO_QKV, qkv_b, nullptr, nullptr, qkv, nullptr, 0, 576);
    // attention
    attn_spatial_kernel<<<4096 * 6, 128>>>(qkv, osp);
    attn_temporal_kernel<<<(Bv * Lv * 6) / 8, 256>>>(qkv, ot);
    // proj + residual
    mma_gemm<192, 2><<<dim3(MT, 2), 256, DSMEM>>>(
        osp, whi + WO_PSP, proj_sp_b, x, xsp, nullptr, nullptr, 0, 192);
    mma_gemm<192, 2><<<dim3(MT, 2), 256, DSMEM>>>(
        ot, whi + WO_PT, proj_t_b, x, xt, nullptr, nullptr, 0, 192);
    // temporal MLP (fc2 also emits concat slot 0)
    ln_apply_kernel<<<Mv / 8, 256>>>(xt, norm2_g, norm2_b, a);
    mma_gemm<192, 4><<<dim3(MT, 8), 256, DSMEM>>>(
        a, whi + WO_TF1, te_fc1_b, nullptr, nullptr, hb, nullptr, 0, HIDv);
    mma_gemm<768, 2><<<dim3(MT, 2), 256, DSMEM>>>(
        hb, whi + WO_TF2, te_fc2_b, xt, xt, nullptr, cat, 0, 192);
    // spatial MLP (fc2 emits concat slot 192)
    ln_apply_kernel<<<Mv / 8, 256>>>(xsp, norm2_g, norm2_b, a);
    mma_gemm<192, 4><<<dim3(MT, 8), 256, DSMEM>>>(
        a, whi + WO_SF1, sp_fc1_b, nullptr, nullptr, hb, nullptr, 0, HIDv);
    mma_gemm<768, 2><<<dim3(MT, 2), 256, DSMEM>>>(
        hb, whi + WO_SF2, sp_fc2_b, xsp, xsp, nullptr, cat, 192, 192);
    // fuse
    mma_gemm<384, 0><<<dim3(MT, 2), 256, DSMEM>>>(
        cat, whi + WO_FUSE, fuse_b, nullptr, out, nullptr, nullptr, 0, 192);
}

// round 14
// speedup vs baseline: 1.3847x; 1.0316x over previous
#include <cuda_runtime.h>
#include <cuda_fp16.h>
#include <math.h>
#include <stdint.h>

// ---------------- problem constants ----------------
constexpr int Bv = 8, Tv = 8, Hv = 56, Wv = 56, Cv = 192;
constexpr int NHv = 6, Lv = Hv * Wv;                // 3136
constexpr int HIDv = 4 * Cv;                        // 768
constexpr int Mv = Bv * Tv * Lv;                    // 200704 tokens
constexpr long MCl = (long)Mv * Cv;
constexpr float QSCALE = 0.17677669529663687f;      // 32^-0.5

// ---------------- device scratch ----------------
__device__ __half g_qkv[(long)Mv * 576];
__device__ __half g_a[MCl];
__device__ __half g_osp[MCl];
__device__ __half g_ot[MCl];
__device__ __half g_h[(long)Mv * HIDv];
__device__ __half g_cat[(long)Mv * 384];
__device__ __half g_whi[847872];
__device__ float g_xt_fb[MCl];
__device__ float g_xsp_fb[MCl];

// weight offsets
constexpr int WO_QKV = 0;            // 576x192
constexpr int WO_PSP = 110592;       // 192x192
constexpr int WO_PT  = 147456;       // 192x192
constexpr int WO_TF1 = 184320;       // 768x192
constexpr int WO_TF2 = 331776;       // 192x768
constexpr int WO_SF1 = 479232;       // 768x192
constexpr int WO_SF2 = 626688;       // 192x768
constexpr int WO_FUSE = 774144;      // 192x384

// ---------------- helpers ----------------
__device__ __forceinline__ uint32_t smem_u32(const void* p) {
    uint32_t a;
    asm("{ .reg .u64 t; cvta.to.shared.u64 t, %1; cvt.u32.u64 %0, t; }" : "=r"(a) : "l"(p));
    return a;
}
__device__ __forceinline__ uint32_t pack_h2(float x, float y) {
    __half2 h = __floats2half2_rn(x, y);
    return *reinterpret_cast<uint32_t*>(&h);
}

#define LDSM4(r, addr)                                                        \
    asm volatile("ldmatrix.sync.aligned.m8n8.x4.shared.b16 {%0,%1,%2,%3}, [%4];" \
        : "=r"((r)[0]), "=r"((r)[1]), "=r"((r)[2]), "=r"((r)[3]) : "r"(addr))

#define LDSM4T(r, addr)                                                       \
    asm volatile("ldmatrix.sync.aligned.m8n8.x4.trans.shared.b16 {%0,%1,%2,%3}, [%4];" \
        : "=r"((r)[0]), "=r"((r)[1]), "=r"((r)[2]), "=r"((r)[3]) : "r"(addr))

#define MMA_F16(c, a, b0, b1)                                                 \
    asm volatile("mma.sync.aligned.m16n8k16.row.col.f32.f16.f16.f32 "         \
        "{%0,%1,%2,%3},{%4,%5,%6,%7},{%8,%9},{%0,%1,%2,%3};"                  \
        : "+f"((c)[0]), "+f"((c)[1]), "+f"((c)[2]), "+f"((c)[3])              \
        : "r"((a)[0]), "r"((a)[1]), "r"((a)[2]), "r"((a)[3]), "r"(b0), "r"(b1))

#define CP16(smem, gptr)                                                      \
    asm volatile("cp.async.cg.shared.global [%0], [%1], 16;"                  \
        :: "r"(smem), "l"(gptr) : "memory")
#define CP_COMMIT() asm volatile("cp.async.commit_group;" ::: "memory")
#define CP_WAIT1()  asm volatile("cp.async.wait_group 1;" ::: "memory")

// ---------------- fp16 pipelined GEMM, CTA tile 128x96, K=32/stage, 3-stage ring ----
// (frozen round-9/11 configuration — known best)
constexpr int STAGE = 17920;
constexpr int NSTG = 3;
constexpr int DSMEM = NSTG * STAGE;

template <int KD, int EM>
__global__ void __launch_bounds__(256, 2)
mma_gemm(const __half* __restrict__ A, const __half* __restrict__ W,
         const float* __restrict__ bias, const float* __restrict__ R,
         float* __restrict__ Y, __half* __restrict__ Yh,
         __half* __restrict__ Cat, int catoff, int N) {
    extern __shared__ char sm[];
    const int tid = threadIdx.x;
    const long m0 = (long)blockIdx.x * 128;
    const int n0 = blockIdx.y * 96;
    constexpr int NS = KD / 32;
    const uint32_t smb = smem_u32(sm);

    const int ar = tid >> 1, aoff = (tid & 1) * 32;
    const int br = tid >> 1, boff = (tid & 1) * 32;
    const bool bact = tid < 192;

    auto fill = [&](int s) {
        const int buf = s % NSTG;
        const uint32_t sb = smb + buf * STAGE;
        {
            const char* g = reinterpret_cast<const char*>(A + (m0 + ar) * (long)KD + s * 32) + aoff;
            uint32_t d = sb + ar * 80 + aoff;
            CP16(d, g); CP16(d + 16, g + 16);
        }
        if (bact) {
            const char* g = reinterpret_cast<const char*>(W + (long)(n0 + br) * KD + s * 32) + boff;
            uint32_t d = sb + 10240 + br * 80 + boff;
            CP16(d, g); CP16(d + 16, g + 16);
        }
    };

    const int l = tid & 31, wid = tid >> 5;
    const int wm = wid & 3, wn = wid >> 2;
    const int arow = wm * 32 + (l & 15);
    const int acol8 = (l >> 4) * 8;
    const int brow = wn * 48 + (l & 7) + ((l >> 4) << 3);
    const int bcol8 = ((l >> 3) & 1) * 8;

    float acc[2][6][4];
#pragma unroll
    for (int i = 0; i < 2; i++)
#pragma unroll
        for (int j = 0; j < 6; j++)
#pragma unroll
            for (int k = 0; k < 4; k++) acc[i][j][k] = 0.f;

    auto mmastage = [&](int buf) {
        const uint32_t base = smb + buf * STAGE;
#pragma unroll
        for (int kt = 0; kt < 2; kt++) {
            uint32_t af[2][4];
#pragma unroll
            for (int mt = 0; mt < 2; mt++)
                LDSM4(af[mt], base + (arow + mt * 16) * 80 + (kt * 16 + acol8) * 2);
#pragma unroll
            for (int nt = 0; nt < 3; nt++) {
                uint32_t bf[4];
                LDSM4(bf, base + 10240 + (brow + nt * 16) * 80 + (kt * 16 + bcol8) * 2);
#pragma unroll
                for (int mt = 0; mt < 2; mt++)
#pragma unroll
                    for (int jj = 0; jj < 2; jj++)
                        MMA_F16(acc[mt][nt * 2 + jj], af[mt], bf[2 * jj], bf[2 * jj + 1]);
            }
        }
    };

    fill(0); CP_COMMIT();
    fill(1); CP_COMMIT();
    for (int s = 0; s < NS; s++) {
        CP_WAIT1();
        __syncthreads();
        mmastage(s % NSTG);
        if (s + 2 < NS) fill(s + 2);
        CP_COMMIT();
    }

    const int g = l >> 2, tg = l & 3;
#pragma unroll
    for (int mt = 0; mt < 2; mt++)
#pragma unroll
        for (int nn = 0; nn < 6; nn++) {
            const int col = n0 + wn * 48 + nn * 8 + 2 * tg;
            const float b0 = bias[col], b1 = bias[col + 1];
#pragma unroll
            for (int h = 0; h < 2; h++) {
                const long row = m0 + wm * 32 + mt * 16 + g + 8 * h;
                float vx = acc[mt][nn][2 * h] + b0;
                float vy = acc[mt][nn][2 * h + 1] + b1;
                if (EM == 1) {
                    if (col < 192) { vx *= QSCALE; vy *= QSCALE; }
                    reinterpret_cast<uint32_t*>(Yh)[(row * (long)N + col) >> 1] = pack_h2(vx, vy);
                }
                if (EM == 0) {
                    *reinterpret_cast<float2*>(Y + row * (long)N + col) = make_float2(vx, vy);
                }
                if (EM == 2) {
                    float2 rv = *reinterpret_cast<const float2*>(R + row * (long)N + col);
                    vx += rv.x; vy += rv.y;
                    *reinterpret_cast<float2*>(Y + row * (long)N + col) = make_float2(vx, vy);
                    if (Cat) {
                        reinterpret_cast<uint32_t*>(Cat)[(row * 384 + catoff + col) >> 1] =
                            pack_h2(vx, vy);
                    }
                }
                if (EM == 4) {
                    vx = 0.5f * vx * (1.0f + erff(vx * 0.70710678118654752f));
                    vy = 0.5f * vy * (1.0f + erff(vy * 0.70710678118654752f));
                    reinterpret_cast<uint32_t*>(Yh)[(row * (long)N + col) >> 1] = pack_h2(vx, vy);
                }
            }
        }
}

// ---------------- combined weight preconversion (fp16 single plane) ----------------
__global__ void w_conv_all_kernel(const float* qkv_w, const float* psp_w, const float* pt_w,
                                  const float* tf1_w, const float* tf2_w, const float* sf1_w,
                                  const float* sf2_w, const float* fuse_w,
                                  __half* __restrict__ hi) {
    int i = blockIdx.x * 256 + threadIdx.x;
    if (i >= 847872) return;
    float v;
    if (i < WO_PSP)       v = qkv_w[i - WO_QKV];
    else if (i < WO_PT)   v = psp_w[i - WO_PSP];
    else if (i < WO_TF1)  v = pt_w[i - WO_PT];
    else if (i < WO_TF2)  v = tf1_w[i - WO_TF1];
    else if (i < WO_SF1)  v = tf2_w[i - WO_TF2];
    else if (i < WO_SF2)  v = sf1_w[i - WO_SF1];
    else if (i < WO_FUSE) v = sf2_w[i - WO_SF2];
    else                  v = fuse_w[i - WO_FUSE];
    hi[i] = __float2half_rn(v);
}

// ---------------- LN fused stats+apply -> fp16 ----------------
__global__ void ln_apply_kernel(const float* __restrict__ X,
                                const float* __restrict__ gamma, const float* __restrict__ beta,
                                __half* __restrict__ O) {
    int tok = blockIdx.x * 8 + (threadIdx.x >> 5);
    int lane = threadIdx.x & 31;
    const float* p = X + (long)tok * Cv;
    float v[6];
#pragma unroll
    for (int i = 0; i < 6; i++) v[i] = p[lane + i * 32];
    float s = v[0] + v[1] + v[2] + v[3] + v[4] + v[5];
#pragma unroll
    for (int o = 16; o > 0; o >>= 1) s += __shfl_xor_sync(~0u, s, o);
    float mu = s * (1.0f / Cv);
    float qv = 0.f;
#pragma unroll
    for (int i = 0; i < 6; i++) { float d = v[i] - mu; qv += d * d; }
#pragma unroll
    for (int o = 16; o > 0; o >>= 1) qv += __shfl_xor_sync(~0u, qv, o);
    float rs = rsqrtf(qv * (1.0f / Cv) + 1e-5f);
#pragma unroll
    for (int i = 0; i < 6; i++) {
        int c = lane + i * 32;
        O[(long)tok * Cv + c] = __float2half_rn((v[i] - mu) * rs * gamma[c] + beta[c]);
    }
}

// ---------------- spatial window attention on tensor cores (smem overlay) ----------
// One CTA per (window-frame, head). 128 threads = 4 warps; rows padded 49->64.
// Qs/Ks/Vs fp16 [64][40] (80B rows); sc fp32 [64][57].
// P (fp16, 64 rows x 72 halfs, 144B stride) OVERLAYS the Q+K region (dead after
// scores): 9216 B <= 10240 B. smem 29.9 KB -> 6 CTAs/SM.
__global__ void __launch_bounds__(128, 6) attn_spatial_kernel(const __half* __restrict__ qkv,
                                                              __half* __restrict__ O) {
    __shared__ __half QKVs[3][64][40];
    __shared__ float sc[64][57];
    __half (*Qs)[40] = QKVs[0];
    __half (*Ks)[40] = QKVs[1];
    __half (*Vs)[40] = QKVs[2];

    const int gh = blockIdx.x;
    const int g = gh / 6, h = gh % 6;
    const int b = g >> 9;
    const int rem = g & 511;
    const int win = rem >> 3, t = rem & 7;
    const int wh = win >> 3, ww = win & 7;
    const int tid = threadIdx.x;
    const int l = tid & 31, w = tid >> 5;
    const long frame = (long)(b * 8 + t) * Lv;

    // zero Vs pad rows 49..63 (15 rows x 20 uint32)
    for (int z = tid; z < 15 * 20; z += 128)
        reinterpret_cast<uint32_t*>(&Vs[49 + z / 20][0])[z % 20] = 0;

    // load q/k/v: 49 tokens x 3 x 4 chunks of 8 halfs (16B)
    for (int u = tid; u < 49 * 12; u += 128) {
        const int i = u / 12, c = u % 12;
        const int seg = c >> 2, cc = c & 3;            // seg: 0=q,1=k,2=v
        const int ltok = (wh * 7 + i / 7) * 56 + ww * 7 + (i % 7);
        const long base = (frame + ltok) * 576 + seg * 192 + h * 32 + cc * 8;
        uint4 v = *reinterpret_cast<const uint4*>(qkv + base);
        *reinterpret_cast<uint4*>(&QKVs[seg][i][cc * 8]) = v;
    }
    __syncthreads();

    const uint32_t q_b = smem_u32(Qs), k_b = smem_u32(Ks), v_b = smem_u32(Vs);
    const uint32_t p_b = q_b;                          // P overlays Q+K
    __half* Pp = &Qs[0][0];

    // ---- scores: S[64x56] = Q @ K^T (per warp: 16 rows x 7 n-tiles) ----
    {
        float acc[7][4];
#pragma unroll
        for (int nt = 0; nt < 7; nt++)
#pragma unroll
            for (int k = 0; k < 4; k++) acc[nt][k] = 0.f;

        const int abrow = w * 16 + (l & 15);
        const int bq = (l & 7) + ((l >> 4) << 3);
        const int bk8 = ((l >> 3) & 1) * 8;
#pragma unroll
        for (int kt = 0; kt < 2; kt++) {
            uint32_t af[4];
            LDSM4(af, q_b + abrow * 80 + (kt * 16 + (l >> 4) * 8) * 2);
#pragma unroll
            for (int np = 0; np < 4; np++) {
                uint32_t bf[4];
                LDSM4(bf, k_b + (np * 16 + bq) * 80 + (kt * 16 + bk8) * 2);
                MMA_F16(acc[np * 2], af, bf[0], bf[1]);
                if (np < 3) MMA_F16(acc[np * 2 + 1], af, bf[2], bf[3]);
            }
        }
        const int r0 = w * 16 + (l >> 2), c0 = 2 * (l & 3);
#pragma unroll
        for (int nt = 0; nt < 7; nt++) {
            sc[r0][nt * 8 + c0] = acc[nt][0];
            sc[r0][nt * 8 + c0 + 1] = acc[nt][1];
            sc[r0 + 8][nt * 8 + c0] = acc[nt][2];
            sc[r0 + 8][nt * 8 + c0 + 1] = acc[nt][3];
        }
    }
    __syncthreads();   // Q/K fully consumed; P overlay now safe

    // ---- softmax rows 0..48 -> P fp16; threads >=49 zero P pad rows ----
    if (tid < 49) {
        float mx = -1e30f;
#pragma unroll 1
        for (int j = 0; j < 49; j++) mx = fmaxf(mx, sc[tid][j]);
        float sum = 0.f;
#pragma unroll 1
        for (int j = 0; j < 49; j++) { float e = __expf(sc[tid][j] - mx); sc[tid][j] = e; sum += e; }
        float inv = 1.0f / sum;
        uint32_t* prow = reinterpret_cast<uint32_t*>(Pp + tid * 72);
#pragma unroll 1
        for (int jj = 0; jj < 24; jj++)
            prow[jj] = pack_h2(sc[tid][2 * jj] * inv, sc[tid][2 * jj + 1] * inv);
        prow[24] = pack_h2(sc[tid][48] * inv, 0.f);
#pragma unroll
        for (int jj = 25; jj < 32; jj++) prow[jj] = 0u;
    } else {
        // zero P pad rows 49..63: 15 rows x 36 uint32 = 540 words over 79 threads
        for (int z = tid - 49; z < 540; z += 79) {
            int r = 49 + z / 36, c = z % 36;
            reinterpret_cast<uint32_t*>(Pp + r * 72)[c] = 0u;
        }
    }
    __syncthreads();

    // ---- AV: O[64x32] = P @ V (per warp: 16 rows x 4 n-tiles, K=64) ----
    {
        float acc2[4][4];
#pragma unroll
        for (int nt = 0; nt < 4; nt++)
#pragma unroll
            for (int k = 0; k < 4; k++) acc2[nt][k] = 0.f;

        const int arow = w * 16 + (l & 15);
#pragma unroll
        for (int kt = 0; kt < 4; kt++) {
            uint32_t af[4];
            LDSM4(af, p_b + arow * 144 + (kt * 16 + (l >> 4) * 8) * 2);
#pragma unroll
            for (int np = 0; np < 2; np++) {
                uint32_t bt[4];
                LDSM4T(bt, v_b + (kt * 16 + (l & 15)) * 80 + (np * 16 + ((l >> 4) & 1) * 8) * 2);
                MMA_F16(acc2[np * 2], af, bt[0], bt[1]);
                MMA_F16(acc2[np * 2 + 1], af, bt[2], bt[3]);
            }
        }
        const int r0 = w * 16 + (l >> 2), c0 = 2 * (l & 3);
#pragma unroll
        for (int half = 0; half < 2; half++) {
            const int i = r0 + half * 8;
            if (i < 49) {
                const int ltok = (wh * 7 + i / 7) * 56 + ww * 7 + (i % 7);
                const long base = (frame + ltok) * 192 + h * 32;
#pragma unroll
                for (int nt = 0; nt < 4; nt++)
                    reinterpret_cast<uint32_t*>(O + base + nt * 8 + c0)[0] =
                        pack_h2(acc2[nt][2 * half], acc2[nt][2 * half + 1]);
            }
        }
    }
}

// ---------------- temporal attention (fp16 qkv in) -> fp16 out ----------------
__global__ void __launch_bounds__(256) attn_temporal_kernel(const __half* __restrict__ qkv,
                                                            __half* __restrict__ O) {
    const int unit = blockIdx.x * 8 + (threadIdx.x >> 5);
    const int lane = threadIdx.x & 31;
    const int g = unit / 6, h = unit % 6;
    const int b = g / Lv, l = g % Lv;
    const long base0 = ((long)(b * 8) * Lv + l) * 576 + h * 32 + lane;
    const long tstride = (long)Lv * 576;

    float q[8], k[8], v[8];
#pragma unroll
    for (int t = 0; t < 8; t++) {
        long base = base0 + (long)t * tstride;
        q[t] = __half2float(qkv[base]);
        k[t] = __half2float(qkv[base + 192]);
        v[t] = __half2float(qkv[base + 384]);
    }
#pragma unroll
    for (int t1 = 0; t1 < 8; t1++) {
        float s[8];
#pragma unroll
        for (int t2 = 0; t2 < 8; t2++) s[t2] = q[t1] * k[t2];
#pragma unroll
        for (int o = 16; o > 0; o >>= 1) {
#pragma unroll
            for (int t2 = 0; t2 < 8; t2++) s[t2] += __shfl_xor_sync(~0u, s[t2], o);
        }
        float mx = s[0];
#pragma unroll
        for (int t2 = 1; t2 < 8; t2++) mx = fmaxf(mx, s[t2]);
        float sum = 0.f;
#pragma unroll
        for (int t2 = 0; t2 < 8; t2++) { s[t2] = __expf(s[t2] - mx); sum += s[t2]; }
        float inv = 1.0f / sum;
        float o = 0.f;
#pragma unroll
        for (int t2 = 0; t2 < 8; t2++) o += s[t2] * v[t2];
        O[((long)(b * 8 + t1) * Lv + l) * 192 + h * 32 + lane] = __float2half_rn(o * inv);
    }
}

// ---------------- launcher ----------------
extern "C" void kernel_launch(void* const* d_in, const int* in_sizes, int n_in,
                              void* d_out, int out_size) {
    (void)in_sizes; (void)n_in;
    const float* x        = (const float*)d_in[0];
    const float* norm1_g  = (const float*)d_in[2];
    const float* norm1_b  = (const float*)d_in[3];
    const float* qkv_w    = (const float*)d_in[4];
    const float* qkv_b    = (const float*)d_in[5];
    const float* proj_sp_w = (const float*)d_in[6];
    const float* proj_sp_b = (const float*)d_in[7];
    const float* proj_t_w = (const float*)d_in[8];
    const float* proj_t_b = (const float*)d_in[9];
    const float* norm2_g  = (const float*)d_in[10];
    const float* norm2_b  = (const float*)d_in[11];
    const float* te_fc1_w = (const float*)d_in[12];
    const float* te_fc1_b = (const float*)d_in[13];
    const float* te_fc2_w = (const float*)d_in[14];
    const float* te_fc2_b = (const float*)d_in[15];
    const float* sp_fc1_w = (const float*)d_in[16];
    const float* sp_fc1_b = (const float*)d_in[17];
    const float* sp_fc2_w = (const float*)d_in[18];
    const float* sp_fc2_b = (const float*)d_in[19];
    const float* fuse_w   = (const float*)d_in[20];
    const float* fuse_b   = (const float*)d_in[21];

    float* out = (float*)d_out;
    float *xt, *xsp;
    if ((long)out_size >= 3 * MCl) {
        xt = out + MCl;
        xsp = out + 2 * MCl;
    } else {
        void* p;
        cudaGetSymbolAddress(&p, g_xt_fb);  xt = (float*)p;
        cudaGetSymbolAddress(&p, g_xsp_fb); xsp = (float*)p;
    }
    void* p;
    cudaGetSymbolAddress(&p, g_qkv);  __half* qkv = (__half*)p;
    cudaGetSymbolAddress(&p, g_a);    __half* a = (__half*)p;
    cudaGetSymbolAddress(&p, g_osp);  __half* osp = (__half*)p;
    cudaGetSymbolAddress(&p, g_ot);   __half* ot = (__half*)p;
    cudaGetSymbolAddress(&p, g_h);    __half* hb = (__half*)p;
    cudaGetSymbolAddress(&p, g_cat);  __half* cat = (__half*)p;
    cudaGetSymbolAddress(&p, g_whi);  __half* whi = (__half*)p;

    cudaFuncSetAttribute(mma_gemm<192, 1>, cudaFuncAttributeMaxDynamicSharedMemorySize, DSMEM);
    cudaFuncSetAttribute(mma_gemm<192, 2>, cudaFuncAttributeMaxDynamicSharedMemorySize, DSMEM);
    cudaFuncSetAttribute(mma_gemm<192, 4>, cudaFuncAttributeMaxDynamicSharedMemorySize, DSMEM);
    cudaFuncSetAttribute(mma_gemm<768, 2>, cudaFuncAttributeMaxDynamicSharedMemorySize, DSMEM);
    cudaFuncSetAttribute(mma_gemm<384, 0>, cudaFuncAttributeMaxDynamicSharedMemorySize, DSMEM);

    const int MT = Mv / 128;  // 1568

    w_conv_all_kernel<<<(847872 + 255) / 256, 256>>>(
        qkv_w, proj_sp_w, proj_t_w, te_fc1_w, te_fc2_w, sp_fc1_w, sp_fc2_w, fuse_w, whi);
    ln_apply_kernel<<<Mv / 8, 256>>>(x, norm1_g, norm1_b, a);
    // QKV (N=576) -> fp16
    mma_gemm<192, 1><<<dim3(MT, 6), 256, DSMEM>>>(
        a, whi + WO_QKV, qkv_b, nullptr, nullptr, qkv, nullptr, 0, 576);
    // attention
    attn_spatial_kernel<<<4096 * 6, 128>>>(qkv, osp);
    attn_temporal_kernel<<<(Bv * Lv * 6) / 8, 256>>>(qkv, ot);
    // proj + residual
    mma_gemm<192, 2><<<dim3(MT, 2), 256, DSMEM>>>(
        osp, whi + WO_PSP, proj_sp_b, x, xsp, nullptr, nullptr, 0, 192);
    mma_gemm<192, 2><<<dim3(MT, 2), 256, DSMEM>>>(
        ot, whi + WO_PT, proj_t_b, x, xt, nullptr, nullptr, 0, 192);
    // temporal MLP (fc2 also emits concat slot 0)
    ln_apply_kernel<<<Mv / 8, 256>>>(xt, norm2_g, norm2_b, a);
    mma_gemm<192, 4><<<dim3(MT, 8), 256, DSMEM>>>(
        a, whi + WO_TF1, te_fc1_b, nullptr, nullptr, hb, nullptr, 0, HIDv);
    mma_gemm<768, 2><<<dim3(MT, 2), 256, DSMEM>>>(
        hb, whi + WO_TF2, te_fc2_b, xt, xt, nullptr, cat, 0, 192);
    // spatial MLP (fc2 emits concat slot 192)
    ln_apply_kernel<<<Mv / 8, 256>>>(xsp, norm2_g, norm2_b, a);
    mma_gemm<192, 4><<<dim3(MT, 8), 256, DSMEM>>>(
        a, whi + WO_SF1, sp_fc1_b, nullptr, nullptr, hb, nullptr, 0, HIDv);
    mma_gemm<768, 2><<<dim3(MT, 2), 256, DSMEM>>>(
        hb, whi + WO_SF2, sp_fc2_b, xsp, xsp, nullptr, cat, 192, 192);
    // fuse
    mma_gemm<384, 0><<<dim3(MT, 2), 256, DSMEM>>>(
        cat, whi + WO_FUSE, fuse_b, nullptr, out, nullptr, nullptr, 0, 192);
}

// round 15
// speedup vs baseline: 1.4475x; 1.0454x over previous
#include <cuda_runtime.h>
#include <cuda_fp16.h>
#include <math.h>
#include <stdint.h>

// ---------------- problem constants ----------------
constexpr int Bv = 8, Tv = 8, Hv = 56, Wv = 56, Cv = 192;
constexpr int NHv = 6, Lv = Hv * Wv;                // 3136
constexpr int HIDv = 4 * Cv;                        // 768
constexpr int Mv = Bv * Tv * Lv;                    // 200704 tokens
constexpr long MCl = (long)Mv * Cv;
constexpr float QSCALE = 0.17677669529663687f;      // 32^-0.5

// ---------------- device scratch ----------------
__device__ __half g_qkv[(long)Mv * 576];
__device__ __half g_a[MCl];
__device__ __half g_osp[MCl];
__device__ __half g_ot[MCl];
__device__ __half g_h[(long)Mv * HIDv];
__device__ __half g_cat[(long)Mv * 384];
__device__ __half g_whi[847872];
__device__ float g_xt_fb[MCl];
__device__ float g_xsp_fb[MCl];

// weight offsets
constexpr int WO_QKV = 0;            // 576x192
constexpr int WO_PSP = 110592;       // 192x192
constexpr int WO_PT  = 147456;       // 192x192
constexpr int WO_TF1 = 184320;       // 768x192
constexpr int WO_TF2 = 331776;       // 192x768
constexpr int WO_SF1 = 479232;       // 768x192
constexpr int WO_SF2 = 626688;       // 192x768
constexpr int WO_FUSE = 774144;      // 192x384

// ---------------- helpers ----------------
__device__ __forceinline__ uint32_t smem_u32(const void* p) {
    uint32_t a;
    asm("{ .reg .u64 t; cvta.to.shared.u64 t, %1; cvt.u32.u64 %0, t; }" : "=r"(a) : "l"(p));
    return a;
}
__device__ __forceinline__ uint32_t pack_h2(float x, float y) {
    __half2 h = __floats2half2_rn(x, y);
    return *reinterpret_cast<uint32_t*>(&h);
}

#define LDSM4(r, addr)                                                        \
    asm volatile("ldmatrix.sync.aligned.m8n8.x4.shared.b16 {%0,%1,%2,%3}, [%4];" \
        : "=r"((r)[0]), "=r"((r)[1]), "=r"((r)[2]), "=r"((r)[3]) : "r"(addr))

#define LDSM4T(r, addr)                                                       \
    asm volatile("ldmatrix.sync.aligned.m8n8.x4.trans.shared.b16 {%0,%1,%2,%3}, [%4];" \
        : "=r"((r)[0]), "=r"((r)[1]), "=r"((r)[2]), "=r"((r)[3]) : "r"(addr))

#define MMA_F16(c, a, b0, b1)                                                 \
    asm volatile("mma.sync.aligned.m16n8k16.row.col.f32.f16.f16.f32 "         \
        "{%0,%1,%2,%3},{%4,%5,%6,%7},{%8,%9},{%0,%1,%2,%3};"                  \
        : "+f"((c)[0]), "+f"((c)[1]), "+f"((c)[2]), "+f"((c)[3])              \
        : "r"((a)[0]), "r"((a)[1]), "r"((a)[2]), "r"((a)[3]), "r"(b0), "r"(b1))

#define CP16(smem, gptr)                                                      \
    asm volatile("cp.async.cg.shared.global [%0], [%1], 16;"                  \
        :: "r"(smem), "l"(gptr) : "memory")
#define CP_COMMIT() asm volatile("cp.async.commit_group;" ::: "memory")
#define CP_WAIT2()  asm volatile("cp.async.wait_group 2;" ::: "memory")

// ---------------- fp16 pipelined GEMM, CTA tile 128x96, K=32/stage, 4-stage ring ----
// smem stage (80B rows): A 0 (128x64B) | W 10240 (96x64B); stage 17920; ring 4.
// wait_group 2 -> two stages resident + one in flight (deeper pipeline, same stage size).
constexpr int STAGE = 17920;
constexpr int NSTG = 4;
constexpr int DSMEM = NSTG * STAGE;   // 71680 B; 2 CTA/SM = 143KB <= 228KB

template <int KD, int EM>
__global__ void __launch_bounds__(256, 2)
mma_gemm(const __half* __restrict__ A, const __half* __restrict__ W,
         const float* __restrict__ bias, const float* __restrict__ R,
         float* __restrict__ Y, __half* __restrict__ Yh,
         __half* __restrict__ Cat, int catoff, int N) {
    extern __shared__ char sm[];
    const int tid = threadIdx.x;
    const long m0 = (long)blockIdx.x * 128;
    const int n0 = blockIdx.y * 96;
    constexpr int NS = KD / 32;
    const uint32_t smb = smem_u32(sm);

    const int ar = tid >> 1, aoff = (tid & 1) * 32;
    const int br = tid >> 1, boff = (tid & 1) * 32;
    const bool bact = tid < 192;

    auto fill = [&](int s) {
        const int buf = s % NSTG;
        const uint32_t sb = smb + buf * STAGE;
        {
            const char* g = reinterpret_cast<const char*>(A + (m0 + ar) * (long)KD + s * 32) + aoff;
            uint32_t d = sb + ar * 80 + aoff;
            CP16(d, g); CP16(d + 16, g + 16);
        }
        if (bact) {
            const char* g = reinterpret_cast<const char*>(W + (long)(n0 + br) * KD + s * 32) + boff;
            uint32_t d = sb + 10240 + br * 80 + boff;
            CP16(d, g); CP16(d + 16, g + 16);
        }
    };

    const int l = tid & 31, wid = tid >> 5;
    const int wm = wid & 3, wn = wid >> 2;
    const int arow = wm * 32 + (l & 15);
    const int acol8 = (l >> 4) * 8;
    const int brow = wn * 48 + (l & 7) + ((l >> 4) << 3);
    const int bcol8 = ((l >> 3) & 1) * 8;

    float acc[2][6][4];
#pragma unroll
    for (int i = 0; i < 2; i++)
#pragma unroll
        for (int j = 0; j < 6; j++)
#pragma unroll
            for (int k = 0; k < 4; k++) acc[i][j][k] = 0.f;

    auto mmastage = [&](int buf) {
        const uint32_t base = smb + buf * STAGE;
#pragma unroll
        for (int kt = 0; kt < 2; kt++) {
            uint32_t af[2][4];
#pragma unroll
            for (int mt = 0; mt < 2; mt++)
                LDSM4(af[mt], base + (arow + mt * 16) * 80 + (kt * 16 + acol8) * 2);
#pragma unroll
            for (int nt = 0; nt < 3; nt++) {
                uint32_t bf[4];
                LDSM4(bf, base + 10240 + (brow + nt * 16) * 80 + (kt * 16 + bcol8) * 2);
#pragma unroll
                for (int mt = 0; mt < 2; mt++)
#pragma unroll
                    for (int jj = 0; jj < 2; jj++)
                        MMA_F16(acc[mt][nt * 2 + jj], af[mt], bf[2 * jj], bf[2 * jj + 1]);
            }
        }
    };

    fill(0); CP_COMMIT();
    fill(1); CP_COMMIT();
    fill(2); CP_COMMIT();
    for (int s = 0; s < NS; s++) {
        CP_WAIT2();
        __syncthreads();
        mmastage(s % NSTG);
        if (s + 3 < NS) fill(s + 3);
        CP_COMMIT();
    }

    const int g = l >> 2, tg = l & 3;
#pragma unroll
    for (int mt = 0; mt < 2; mt++)
#pragma unroll
        for (int nn = 0; nn < 6; nn++) {
            const int col = n0 + wn * 48 + nn * 8 + 2 * tg;
            const float b0 = bias[col], b1 = bias[col + 1];
#pragma unroll
            for (int h = 0; h < 2; h++) {
                const long row = m0 + wm * 32 + mt * 16 + g + 8 * h;
                float vx = acc[mt][nn][2 * h] + b0;
                float vy = acc[mt][nn][2 * h + 1] + b1;
                if (EM == 1) {
                    if (col < 192) { vx *= QSCALE; vy *= QSCALE; }
                    reinterpret_cast<uint32_t*>(Yh)[(row * (long)N + col) >> 1] = pack_h2(vx, vy);
                }
                if (EM == 0) {
                    *reinterpret_cast<float2*>(Y + row * (long)N + col) = make_float2(vx, vy);
                }
                if (EM == 2) {
                    float2 rv = *reinterpret_cast<const float2*>(R + row * (long)N + col);
                    vx += rv.x; vy += rv.y;
                    *reinterpret_cast<float2*>(Y + row * (long)N + col) = make_float2(vx, vy);
                    if (Cat) {
                        reinterpret_cast<uint32_t*>(Cat)[(row * 384 + catoff + col) >> 1] =
                            pack_h2(vx, vy);
                    }
                }
                if (EM == 4) {
                    vx = 0.5f * vx * (1.0f + erff(vx * 0.70710678118654752f));
                    vy = 0.5f * vy * (1.0f + erff(vy * 0.70710678118654752f));
                    reinterpret_cast<uint32_t*>(Yh)[(row * (long)N + col) >> 1] = pack_h2(vx, vy);
                }
            }
        }
}

// ---------------- combined weight preconversion (fp16 single plane) ----------------
__global__ void w_conv_all_kernel(const float* qkv_w, const float* psp_w, const float* pt_w,
                                  const float* tf1_w, const float* tf2_w, const float* sf1_w,
                                  const float* sf2_w, const float* fuse_w,
                                  __half* __restrict__ hi) {
    int i = blockIdx.x * 256 + threadIdx.x;
    if (i >= 847872) return;
    float v;
    if (i < WO_PSP)       v = qkv_w[i - WO_QKV];
    else if (i < WO_PT)   v = psp_w[i - WO_PSP];
    else if (i < WO_TF1)  v = pt_w[i - WO_PT];
    else if (i < WO_TF2)  v = tf1_w[i - WO_TF1];
    else if (i < WO_SF1)  v = tf2_w[i - WO_TF2];
    else if (i < WO_SF2)  v = sf1_w[i - WO_SF1];
    else if (i < WO_FUSE) v = sf2_w[i - WO_SF2];
    else                  v = fuse_w[i - WO_FUSE];
    hi[i] = __float2half_rn(v);
}

// ---------------- LN fused stats+apply -> fp16 ----------------
__global__ void ln_apply_kernel(const float* __restrict__ X,
                                const float* __restrict__ gamma, const float* __restrict__ beta,
                                __half* __restrict__ O) {
    int tok = blockIdx.x * 8 + (threadIdx.x >> 5);
    int lane = threadIdx.x & 31;
    const float* p = X + (long)tok * Cv;
    float v[6];
#pragma unroll
    for (int i = 0; i < 6; i++) v[i] = p[lane + i * 32];
    float s = v[0] + v[1] + v[2] + v[3] + v[4] + v[5];
#pragma unroll
    for (int o = 16; o > 0; o >>= 1) s += __shfl_xor_sync(~0u, s, o);
    float mu = s * (1.0f / Cv);
    float qv = 0.f;
#pragma unroll
    for (int i = 0; i < 6; i++) { float d = v[i] - mu; qv += d * d; }
#pragma unroll
    for (int o = 16; o > 0; o >>= 1) qv += __shfl_xor_sync(~0u, qv, o);
    float rs = rsqrtf(qv * (1.0f / Cv) + 1e-5f);
#pragma unroll
    for (int i = 0; i < 6; i++) {
        int c = lane + i * 32;
        O[(long)tok * Cv + c] = __float2half_rn((v[i] - mu) * rs * gamma[c] + beta[c]);
    }
}

// ---------------- spatial window attention on tensor cores (smem overlay) ----------
__global__ void __launch_bounds__(128, 6) attn_spatial_kernel(const __half* __restrict__ qkv,
                                                              __half* __restrict__ O) {
    __shared__ __half QKVs[3][64][40];
    __shared__ float sc[64][57];
    __half (*Qs)[40] = QKVs[0];
    __half (*Ks)[40] = QKVs[1];
    __half (*Vs)[40] = QKVs[2];

    const int gh = blockIdx.x;
    const int g = gh / 6, h = gh % 6;
    const int b = g >> 9;
    const int rem = g & 511;
    const int win = rem >> 3, t = rem & 7;
    const int wh = win >> 3, ww = win & 7;
    const int tid = threadIdx.x;
    const int l = tid & 31, w = tid >> 5;
    const long frame = (long)(b * 8 + t) * Lv;

    for (int z = tid; z < 15 * 20; z += 128)
        reinterpret_cast<uint32_t*>(&Vs[49 + z / 20][0])[z % 20] = 0;

    for (int u = tid; u < 49 * 12; u += 128) {
        const int i = u / 12, c = u % 12;
        const int seg = c >> 2, cc = c & 3;
        const int ltok = (wh * 7 + i / 7) * 56 + ww * 7 + (i % 7);
        const long base = (frame + ltok) * 576 + seg * 192 + h * 32 + cc * 8;
        uint4 v = *reinterpret_cast<const uint4*>(qkv + base);
        *reinterpret_cast<uint4*>(&QKVs[seg][i][cc * 8]) = v;
    }
    __syncthreads();

    const uint32_t q_b = smem_u32(Qs), k_b = smem_u32(Ks), v_b = smem_u32(Vs);
    const uint32_t p_b = q_b;
    __half* Pp = &Qs[0][0];

    {
        float acc[7][4];
#pragma unroll
        for (int nt = 0; nt < 7; nt++)
#pragma unroll
            for (int k = 0; k < 4; k++) acc[nt][k] = 0.f;

        const int abrow = w * 16 + (l & 15);
        const int bq = (l & 7) + ((l >> 4) << 3);
        const int bk8 = ((l >> 3) & 1) * 8;
#pragma unroll
        for (int kt = 0; kt < 2; kt++) {
            uint32_t af[4];
            LDSM4(af, q_b + abrow * 80 + (kt * 16 + (l >> 4) * 8) * 2);
#pragma unroll
            for (int np = 0; np < 4; np++) {
                uint32_t bf[4];
                LDSM4(bf, k_b + (np * 16 + bq) * 80 + (kt * 16 + bk8) * 2);
                MMA_F16(acc[np * 2], af, bf[0], bf[1]);
                if (np < 3) MMA_F16(acc[np * 2 + 1], af, bf[2], bf[3]);
            }
        }
        const int r0 = w * 16 + (l >> 2), c0 = 2 * (l & 3);
#pragma unroll
        for (int nt = 0; nt < 7; nt++) {
            sc[r0][nt * 8 + c0] = acc[nt][0];
            sc[r0][nt * 8 + c0 + 1] = acc[nt][1];
            sc[r0 + 8][nt * 8 + c0] = acc[nt][2];
            sc[r0 + 8][nt * 8 + c0 + 1] = acc[nt][3];
        }
    }
    __syncthreads();

    if (tid < 49) {
        float mx = -1e30f;
#pragma unroll 1
        for (int j = 0; j < 49; j++) mx = fmaxf(mx, sc[tid][j]);
        float sum = 0.f;
#pragma unroll 1
        for (int j = 0; j < 49; j++) { float e = __expf(sc[tid][j] - mx); sc[tid][j] = e; sum += e; }
        float inv = 1.0f / sum;
        uint32_t* prow = reinterpret_cast<uint32_t*>(Pp + tid * 72);
#pragma unroll 1
        for (int jj = 0; jj < 24; jj++)
            prow[jj] = pack_h2(sc[tid][2 * jj] * inv, sc[tid][2 * jj + 1] * inv);
        prow[24] = pack_h2(sc[tid][48] * inv, 0.f);
#pragma unroll
        for (int jj = 25; jj < 32; jj++) prow[jj] = 0u;
    } else {
        for (int z = tid - 49; z < 540; z += 79) {
            int r = 49 + z / 36, c = z % 36;
            reinterpret_cast<uint32_t*>(Pp + r * 72)[c] = 0u;
        }
    }
    __syncthreads();

    {
        float acc2[4][4];
#pragma unroll
        for (int nt = 0; nt < 4; nt++)
#pragma unroll
            for (int k = 0; k < 4; k++) acc2[nt][k] = 0.f;

        const int arow = w * 16 + (l & 15);
#pragma unroll
        for (int kt = 0; kt < 4; kt++) {
            uint32_t af[4];
            LDSM4(af, p_b + arow * 144 + (kt * 16 + (l >> 4) * 8) * 2);
#pragma unroll
            for (int np = 0; np < 2; np++) {
                uint32_t bt[4];
                LDSM4T(bt, v_b + (kt * 16 + (l & 15)) * 80 + (np * 16 + ((l >> 4) & 1) * 8) * 2);
                MMA_F16(acc2[np * 2], af, bt[0], bt[1]);
                MMA_F16(acc2[np * 2 + 1], af, bt[2], bt[3]);
            }
        }
        const int r0 = w * 16 + (l >> 2), c0 = 2 * (l & 3);
#pragma unroll
        for (int half = 0; half < 2; half++) {
            const int i = r0 + half * 8;
            if (i < 49) {
                const int ltok = (wh * 7 + i / 7) * 56 + ww * 7 + (i % 7);
                const long base = (frame + ltok) * 192 + h * 32;
#pragma unroll
                for (int nt = 0; nt < 4; nt++)
                    reinterpret_cast<uint32_t*>(O + base + nt * 8 + c0)[0] =
                        pack_h2(acc2[nt][2 * half], acc2[nt][2 * half + 1]);
            }
        }
    }
}

// ---------------- temporal attention: half2, 2 heads per warp ----------------
// Warp handles (pixel, head-pair). Lanes 0-15: head hp*2 (chs 2*lane..+1);
// lanes 16-31: head hp*2+1. Butterfly over 4 steps (8,4,2,1) stays head-local.
__global__ void __launch_bounds__(256) attn_temporal_kernel(const __half* __restrict__ qkv,
                                                            __half* __restrict__ O) {
    const int unit = blockIdx.x * 8 + (threadIdx.x >> 5);
    const int lane = threadIdx.x & 31;
    const int g = unit / 3, hp = unit % 3;
    const int b = g / Lv, l = g % Lv;
    const int head = hp * 2 + (lane >> 4);
    const int ch = (lane & 15) * 2;
    const long base0 = ((long)(b * 8) * Lv + l) * 576 + head * 32 + ch;
    const long tstride = (long)Lv * 576;

    float2 q[8], k[8], v[8];
#pragma unroll
    for (int t = 0; t < 8; t++) {
        long base = base0 + (long)t * tstride;
        q[t] = __half22float2(*reinterpret_cast<const __half2*>(qkv + base));
        k[t] = __half22float2(*reinterpret_cast<const __half2*>(qkv + base + 192));
        v[t] = __half22float2(*reinterpret_cast<const __half2*>(qkv + base + 384));
    }
#pragma unroll
    for (int t1 = 0; t1 < 8; t1++) {
        float s[8];
#pragma unroll
        for (int t2 = 0; t2 < 8; t2++) s[t2] = q[t1].x * k[t2].x + q[t1].y * k[t2].y;
#pragma unroll
        for (int o = 8; o > 0; o >>= 1) {
#pragma unroll
            for (int t2 = 0; t2 < 8; t2++) s[t2] += __shfl_xor_sync(~0u, s[t2], o);
        }
        float mx = s[0];
#pragma unroll
        for (int t2 = 1; t2 < 8; t2++) mx = fmaxf(mx, s[t2]);
        float sum = 0.f;
#pragma unroll
        for (int t2 = 0; t2 < 8; t2++) { s[t2] = __expf(s[t2] - mx); sum += s[t2]; }
        float inv = 1.0f / sum;
        float ox = 0.f, oy = 0.f;
#pragma unroll
        for (int t2 = 0; t2 < 8; t2++) { ox += s[t2] * v[t2].x; oy += s[t2] * v[t2].y; }
        long e = ((long)(b * 8 + t1) * Lv + l) * 192 + head * 32 + ch;
        reinterpret_cast<uint32_t*>(O + e)[0] = pack_h2(ox * inv, oy * inv);
    }
}

// ---------------- launcher ----------------
extern "C" void kernel_launch(void* const* d_in, const int* in_sizes, int n_in,
                              void* d_out, int out_size) {
    (void)in_sizes; (void)n_in;
    const float* x        = (const float*)d_in[0];
    const float* norm1_g  = (const float*)d_in[2];
    const float* norm1_b  = (const float*)d_in[3];
    const float* qkv_w    = (const float*)d_in[4];
    const float* qkv_b    = (const float*)d_in[5];
    const float* proj_sp_w = (const float*)d_in[6];
    const float* proj_sp_b = (const float*)d_in[7];
    const float* proj_t_w = (const float*)d_in[8];
    const float* proj_t_b = (const float*)d_in[9];
    const float* norm2_g  = (const float*)d_in[10];
    const float* norm2_b  = (const float*)d_in[11];
    const float* te_fc1_w = (const float*)d_in[12];
    const float* te_fc1_b = (const float*)d_in[13];
    const float* te_fc2_w = (const float*)d_in[14];
    const float* te_fc2_b = (const float*)d_in[15];
    const float* sp_fc1_w = (const float*)d_in[16];
    const float* sp_fc1_b = (const float*)d_in[17];
    const float* sp_fc2_w = (const float*)d_in[18];
    const float* sp_fc2_b = (const float*)d_in[19];
    const float* fuse_w   = (const float*)d_in[20];
    const float* fuse_b   = (const float*)d_in[21];

    float* out = (float*)d_out;
    float *xt, *xsp;
    if ((long)out_size >= 3 * MCl) {
        xt = out + MCl;
        xsp = out + 2 * MCl;
    } else {
        void* p;
        cudaGetSymbolAddress(&p, g_xt_fb);  xt = (float*)p;
        cudaGetSymbolAddress(&p, g_xsp_fb); xsp = (float*)p;
    }
    void* p;
    cudaGetSymbolAddress(&p, g_qkv);  __half* qkv = (__half*)p;
    cudaGetSymbolAddress(&p, g_a);    __half* a = (__half*)p;
    cudaGetSymbolAddress(&p, g_osp);  __half* osp = (__half*)p;
    cudaGetSymbolAddress(&p, g_ot);   __half* ot = (__half*)p;
    cudaGetSymbolAddress(&p, g_h);    __half* hb = (__half*)p;
    cudaGetSymbolAddress(&p, g_cat);  __half* cat = (__half*)p;
    cudaGetSymbolAddress(&p, g_whi);  __half* whi = (__half*)p;

    cudaFuncSetAttribute(mma_gemm<192, 1>, cudaFuncAttributeMaxDynamicSharedMemorySize, DSMEM);
    cudaFuncSetAttribute(mma_gemm<192, 2>, cudaFuncAttributeMaxDynamicSharedMemorySize, DSMEM);
    cudaFuncSetAttribute(mma_gemm<192, 4>, cudaFuncAttributeMaxDynamicSharedMemorySize, DSMEM);
    cudaFuncSetAttribute(mma_gemm<768, 2>, cudaFuncAttributeMaxDynamicSharedMemorySize, DSMEM);
    cudaFuncSetAttribute(mma_gemm<384, 0>, cudaFuncAttributeMaxDynamicSharedMemorySize, DSMEM);

    const int MT = Mv / 128;  // 1568

    w_conv_all_kernel<<<(847872 + 255) / 256, 256>>>(
        qkv_w, proj_sp_w, proj_t_w, te_fc1_w, te_fc2_w, sp_fc1_w, sp_fc2_w, fuse_w, whi);
    ln_apply_kernel<<<Mv / 8, 256>>>(x, norm1_g, norm1_b, a);
    // QKV (N=576) -> fp16
    mma_gemm<192, 1><<<dim3(MT, 6), 256, DSMEM>>>(
        a, whi + WO_QKV, qkv_b, nullptr, nullptr, qkv, nullptr, 0, 576);
    // attention
    attn_spatial_kernel<<<4096 * 6, 128>>>(qkv, osp);
    attn_temporal_kernel<<<(Bv * Lv * 3) / 8, 256>>>(qkv, ot);
    // proj + residual
    mma_gemm<192, 2><<<dim3(MT, 2), 256, DSMEM>>>(
        osp, whi + WO_PSP, proj_sp_b, x, xsp, nullptr, nullptr, 0, 192);
    mma_gemm<192, 2><<<dim3(MT, 2), 256, DSMEM>>>(
        ot, whi + WO_PT, proj_t_b, x, xt, nullptr, nullptr, 0, 192);
    // temporal MLP (fc2 also emits concat slot 0)
    ln_apply_kernel<<<Mv / 8, 256>>>(xt, norm2_g, norm2_b, a);
    mma_gemm<192, 4><<<dim3(MT, 8), 256, DSMEM>>>(
        a, whi + WO_TF1, te_fc1_b, nullptr, nullptr, hb, nullptr, 0, HIDv);
    mma_gemm<768, 2><<<dim3(MT, 2), 256, DSMEM>>>(
        hb, whi + WO_TF2, te_fc2_b, xt, xt, nullptr, cat, 0, 192);
    // spatial MLP (fc2 emits concat slot 192)
    ln_apply_kernel<<<Mv / 8, 256>>>(xsp, norm2_g, norm2_b, a);
    mma_gemm<192, 4><<<dim3(MT, 8), 256, DSMEM>>>(
        a, whi + WO_SF1, sp_fc1_b, nullptr, nullptr, hb, nullptr, 0, HIDv);
    mma_gemm<768, 2><<<dim3(MT, 2), 256, DSMEM>>>(
        hb, whi + WO_SF2, sp_fc2_b, xsp, xsp, nullptr, cat, 192, 192);
    // fuse
    mma_gemm<384, 0><<<dim3(MT, 2), 256, DSMEM>>>(
        cat, whi + WO_FUSE, fuse_b, nullptr, out, nullptr, nullptr, 0, 192);
}